// round 3
// baseline (speedup 1.0000x reference)
#include <cuda_runtime.h>
#include <float.h>
#include <stdint.h>

#define BATCH 8
#define NPT   2048
#define KNB   16
#define BN    (BATCH*NPT)   // 16384

// ---------------- scratch (__device__ globals: allocation-free) ----------------
__device__ float g_D[(size_t)BATCH*NPT*NPT];   // 134MB distance matrix (reused 3x)
__device__ float g_sq[BN];
__device__ int   g_idx[BN*KNB];
__device__ float g_x2[BN*32];
__device__ float g_x3[BN*128];
__device__ float g_A [BN*256];                 // factored layer-1: ctr-projection (+bias)
__device__ float g_Bf[BN*256];                 // factored layer-1: nbr-projection
__device__ float g_x4[BN*128];
__device__ float g_x5p[BATCH*16*128];

__device__ __forceinline__ float lrelu(float v) { return v >= 0.f ? v : 0.01f*v; }

// ---------------- squared norms (warp per point) ----------------
__global__ void sq_kernel(const float* __restrict__ X, int C) {
    int gw   = (blockIdx.x*blockDim.x + threadIdx.x) >> 5;
    int lane = threadIdx.x & 31;
    if (gw >= BN) return;
    const float* r = X + (size_t)gw*C;
    float acc = 0.f;
    for (int c = lane; c < C; c += 32) { float v = r[c]; acc += v*v; }
    #pragma unroll
    for (int o = 16; o; o >>= 1) acc += __shfl_xor_sync(0xffffffffu, acc, o);
    if (lane == 0) g_sq[gw] = acc;
}

// ---------------- pairwise distance: D = sq_i + sq_j - 2*dot ----------------
// 64x64 tile, 256 threads, 4x4 register microtile (16 FMA per 8 LDS)
template<int C>
__global__ __launch_bounds__(256) void dist_kernel(const float* __restrict__ X) {
    constexpr int CT = (C < 32) ? C : 32;
    __shared__ float As[CT][65];   // +1 pad kills store conflicts
    __shared__ float Bs[CT][65];
    int b  = blockIdx.z;
    int i0 = blockIdx.y * 64, j0 = blockIdx.x * 64;
    const float* Xb = X + (size_t)b*NPT*C;
    int t  = threadIdx.x;
    int tx = t & 15, ty = t >> 4;
    float acc[4][4] = {};
    for (int c0 = 0; c0 < C; c0 += CT) {
        __syncthreads();
        for (int e = t; e < 64*CT; e += 256) {
            int r = e / CT, c = e % CT;
            As[c][r] = Xb[(size_t)(i0 + r)*C + c0 + c];
            Bs[c][r] = Xb[(size_t)(j0 + r)*C + c0 + c];
        }
        __syncthreads();
        #pragma unroll
        for (int c = 0; c < CT; c++) {
            float av[4], bv[4];
            #pragma unroll
            for (int u = 0; u < 4; u++) { av[u] = As[c][ty*4+u]; bv[u] = Bs[c][tx*4+u]; }
            #pragma unroll
            for (int ii = 0; ii < 4; ii++)
                #pragma unroll
                for (int jj = 0; jj < 4; jj++)
                    acc[ii][jj] += av[ii]*bv[jj];
        }
    }
    const float* sqb = g_sq + b*NPT;
    float* Db = g_D + (size_t)b*NPT*NPT;
    int j = j0 + tx*4;
    float s0 = sqb[j+0], s1 = sqb[j+1], s2 = sqb[j+2], s3 = sqb[j+3];
    #pragma unroll
    for (int ii = 0; ii < 4; ii++) {
        int i = i0 + ty*4 + ii;
        float si = sqb[i];
        float4 o;
        o.x = si + s0 - 2.f*acc[ii][0];
        o.y = si + s1 - 2.f*acc[ii][1];
        o.z = si + s2 - 2.f*acc[ii][2];
        o.w = si + s3 - 2.f*acc[ii][3];
        *(float4*)(Db + (size_t)i*NPT + j) = o;
    }
}

// ---------------- top-16 (block per row, iterative argmin in smem) ----------------
#define PHYS(s) ((s) + ((s) >> 5))    // pad: stride-128 scan -> conflict-free banks
__global__ __launch_bounds__(128) void topk_kernel() {
    __shared__ float sd[NPT + 64];
    __shared__ float rbest[4];
    __shared__ int   ribest[4];
    int row = blockIdx.x;
    const float* Dr = g_D + (size_t)row * NPT;
    int t = threadIdx.x;
    for (int s = t; s < NPT; s += 128) sd[PHYS(s)] = Dr[s];
    __syncthreads();
    for (int it = 0; it < KNB; it++) {
        float best = FLT_MAX; int bi = NPT;
        for (int s = t; s < NPT; s += 128) {
            float v = sd[PHYS(s)];
            if (v < best) { best = v; bi = s; }     // strict < keeps lowest index in-thread
        }
        #pragma unroll
        for (int o = 16; o; o >>= 1) {
            float ov = __shfl_down_sync(0xffffffffu, best, o);
            int   oi = __shfl_down_sync(0xffffffffu, bi, o);
            if (ov < best || (ov == best && oi < bi)) { best = ov; bi = oi; }
        }
        if ((t & 31) == 0) { rbest[t>>5] = best; ribest[t>>5] = bi; }
        __syncthreads();
        if (t == 0) {
            #pragma unroll
            for (int w = 1; w < 4; w++)
                if (rbest[w] < best || (rbest[w] == best && ribest[w] < bi)) { best = rbest[w]; bi = ribest[w]; }
            g_idx[row*KNB + it] = bi;
            sd[PHYS(bi)] = FLT_MAX;
        }
        __syncthreads();
    }
}

// ---------------- block 1: edge MLP 6->16->64->32, sum over K ----------------
// thread per (point, k); 8 points / block; weights in smem (broadcast reads)
__global__ __launch_bounds__(128) void mlp1_kernel(
        const float* __restrict__ x,
        const float* __restrict__ w1, const float* __restrict__ b1,
        const float* __restrict__ w2, const float* __restrict__ b2,
        const float* __restrict__ w3, const float* __restrict__ b3) {
    __shared__ float s1[96], sb1[16], s2[1024], sb2[64], s3[2048], sb3[32];
    int t = threadIdx.x;
    if (t < 96) s1[t] = w1[t];
    if (t < 16) sb1[t] = b1[t];
    for (int e = t; e < 1024; e += 128) s2[e] = w2[e];
    if (t < 64) sb2[t] = b2[t];
    for (int e = t; e < 2048; e += 128) s3[e] = w3[e];
    if (t < 32) sb3[t] = b3[t];
    __syncthreads();
    int k = t & 15, lp = t >> 4;
    int p = blockIdx.x * 8 + lp;
    int b = p >> 11;
    int j = g_idx[p*KNB + k];
    float in[6];
    const float* xc = x + (size_t)p*3;
    const float* xn = x + (size_t)(b*NPT + j)*3;
    in[0]=xc[0]; in[1]=xc[1]; in[2]=xc[2];
    in[3]=xn[0]; in[4]=xn[1]; in[5]=xn[2];
    float h16[16];
    #pragma unroll
    for (int o = 0; o < 16; o++) {
        float a = sb1[o];
        #pragma unroll
        for (int c = 0; c < 6; c++) a += s1[c*16+o]*in[c];
        h16[o] = lrelu(a);
    }
    float h64[64];
    #pragma unroll
    for (int o = 0; o < 64; o++) {
        float a = sb2[o];
        #pragma unroll
        for (int c = 0; c < 16; c++) a += s2[c*64+o]*h16[c];
        h64[o] = lrelu(a);
    }
    float h32[32];
    #pragma unroll
    for (int o = 0; o < 32; o++) {
        float a = sb3[o];
        #pragma unroll
        for (int c = 0; c < 64; c++) a += s3[c*32+o]*h64[c];
        h32[o] = lrelu(a);
    }
    // sum over k within 16-lane groups
    #pragma unroll
    for (int c = 0; c < 32; c++) {
        #pragma unroll
        for (int o = 8; o; o >>= 1) h32[c] += __shfl_xor_sync(0xffffffffu, h32[c], o);
    }
    if (k == 0) {
        float* outp = g_x2 + (size_t)p*32;
        #pragma unroll
        for (int c = 0; c < 32; c++) outp[c] = h32[c];
    }
}

// ---------------- factored layer-1 projections: A = X@W[0:CIN]+b, Bf = X@W[CIN:2CIN] ----------------
template<int CIN, int COUT>
__global__ __launch_bounds__(256) void proj_kernel(
        const float* __restrict__ X, const float* __restrict__ W,
        const float* __restrict__ bias) {
    constexpr int OG = COUT/4;
    constexpr int R  = 256/OG;
    __shared__ float sin[R][CIN];
    int t = threadIdx.x;
    int p0 = blockIdx.x * R;
    for (int e = t; e < R*CIN; e += 256) sin[e / CIN][e % CIN] = X[(size_t)p0*CIN + e];
    __syncthreads();
    int og = t % OG, r = t / OG;
    float4 aa = {0,0,0,0}, bb = {0,0,0,0};
    #pragma unroll 4
    for (int c = 0; c < CIN; c++) {
        float v = sin[r][c];
        float4 wa = *(const float4*)(W + (size_t)c*COUT + og*4);
        float4 wb = *(const float4*)(W + (size_t)(CIN + c)*COUT + og*4);
        aa.x += wa.x*v; aa.y += wa.y*v; aa.z += wa.z*v; aa.w += wa.w*v;
        bb.x += wb.x*v; bb.y += wb.y*v; bb.z += wb.z*v; bb.w += wb.w*v;
    }
    float4 b4 = *(const float4*)(bias + og*4);
    aa.x += b4.x; aa.y += b4.y; aa.z += b4.z; aa.w += b4.w;
    *(float4*)(g_A  + (size_t)(p0 + r)*COUT + og*4) = aa;
    *(float4*)(g_Bf + (size_t)(p0 + r)*COUT + og*4) = bb;
}

// ---------------- block 2 heavy kernel: h1[k]=lrelu(A[n]+Bf[j_k]); x3=sum_k lrelu(h1@W2+b2) ----------------
#define MLP2_SMEM ((32768 + 128 + 256 + 4096 + 1024)*4 + KNB*4)
__global__ __launch_bounds__(256) void mlp2_kernel(
        const float* __restrict__ W2, const float* __restrict__ b2) {
    extern __shared__ float sm[];
    float* W2s = sm;                  // 256*128
    float* b2s = W2s + 32768;         // 128
    float* a_s = b2s + 128;           // 256
    float* h1s = a_s + 256;           // 16*256
    float* red = h1s + 4096;          // 8*128
    int*  idxs = (int*)(red + 1024);  // 16
    int t = threadIdx.x;
    for (int e = t; e < 8192; e += 256) ((float4*)W2s)[e] = ((const float4*)W2)[e];
    if (t < 128) b2s[t] = b2[t];
    for (int pp = 0; pp < 8; pp++) {
        int p = blockIdx.x*8 + pp;
        int b = p >> 11;
        __syncthreads();                      // weights (1st iter) / smem reuse (later)
        if (t < KNB) idxs[t] = g_idx[p*KNB + t];
        a_s[t] = g_A[(size_t)p*256 + t];
        __syncthreads();
        {   // layer 1 (factored): gather + add + lrelu
            int k = t >> 4, q = t & 15;
            const float* Br = g_Bf + (size_t)(b*NPT + idxs[k])*256;
            #pragma unroll
            for (int e = 0; e < 4; e++) {
                int c = q*16 + e*4;
                float4 bv = *(const float4*)(Br + c);
                float4 av = *(const float4*)(a_s + c);
                float4 h;
                h.x = lrelu(av.x + bv.x); h.y = lrelu(av.y + bv.y);
                h.z = lrelu(av.z + bv.z); h.w = lrelu(av.w + bv.w);
                *(float4*)(h1s + k*256 + c) = h;
            }
        }
        __syncthreads();
        {   // layer 2: 256 -> 128 per k, lrelu, partial-sum over 2 k's per thread
            int cg = t & 31, kg = t >> 5;
            const float* h0 = h1s + (kg*2)*256;
            const float* h1 = h0 + 256;
            float4 a0 = {0,0,0,0}, a1 = {0,0,0,0};
            #pragma unroll 4
            for (int c = 0; c < 256; c++) {
                float4 w = *(const float4*)(W2s + c*128 + cg*4);
                float v0 = h0[c], v1 = h1[c];
                a0.x += w.x*v0; a0.y += w.y*v0; a0.z += w.z*v0; a0.w += w.w*v0;
                a1.x += w.x*v1; a1.y += w.y*v1; a1.z += w.z*v1; a1.w += w.w*v1;
            }
            float4 bb = *(const float4*)(b2s + cg*4);
            float4 s;
            s.x = lrelu(a0.x+bb.x) + lrelu(a1.x+bb.x);
            s.y = lrelu(a0.y+bb.y) + lrelu(a1.y+bb.y);
            s.z = lrelu(a0.z+bb.z) + lrelu(a1.z+bb.z);
            s.w = lrelu(a0.w+bb.w) + lrelu(a1.w+bb.w);
            *(float4*)(red + kg*128 + cg*4) = s;
        }
        __syncthreads();
        if (t < 128) {
            float sum = 0.f;
            #pragma unroll
            for (int kg = 0; kg < 8; kg++) sum += red[kg*128 + t];
            g_x3[(size_t)p*128 + t] = sum;
        }
    }
}

// ---------------- block 3 (fully factored): x4 = sum_k lrelu(A3[n] + B3[j_k]) ----------------
__global__ __launch_bounds__(128) void block3_kernel() {
    __shared__ int idxs[KNB];
    int p = blockIdx.x, t = threadIdx.x;
    int b = p >> 11;
    if (t < KNB) idxs[t] = g_idx[p*KNB + t];
    __syncthreads();
    float a = g_A[(size_t)p*128 + t];
    float acc = 0.f;
    #pragma unroll
    for (int k = 0; k < KNB; k++)
        acc += lrelu(a + g_Bf[(size_t)(b*NPT + idxs[k])*128 + t]);
    g_x4[(size_t)p*128 + t] = acc;
}

// ---------------- global max pool (partials) ----------------
__global__ __launch_bounds__(128) void maxpool_kernel() {
    int b = blockIdx.x, seg = blockIdx.y, t = threadIdx.x;
    const float* base = g_x4 + ((size_t)b*NPT + seg*128)*128 + t;
    float m = -FLT_MAX;
    #pragma unroll 8
    for (int r = 0; r < 128; r++) m = fmaxf(m, base[(size_t)r*128]);
    g_x5p[(b*16 + seg)*128 + t] = m;
}

// ---------------- final: reduce pool + fc1 + fc2 + fc3 ----------------
__global__ __launch_bounds__(128) void final_kernel(
        const float* __restrict__ fc1w, const float* __restrict__ fc1b,
        const float* __restrict__ fc2w, const float* __restrict__ fc2b,
        const float* __restrict__ fc3w, const float* __restrict__ fc3b,
        float* __restrict__ out) {
    __shared__ float s5[128], s6[128], s7[128];
    int b = blockIdx.x, t = threadIdx.x;
    float m = -FLT_MAX;
    #pragma unroll
    for (int s = 0; s < 16; s++) m = fmaxf(m, g_x5p[(b*16+s)*128 + t]);
    s5[t] = m;
    __syncthreads();
    float a = fc1b[t];
    #pragma unroll 8
    for (int c = 0; c < 128; c++) a += fc1w[c*128+t]*s5[c];
    s6[t] = lrelu(a);
    __syncthreads();
    a = fc2b[t];
    #pragma unroll 8
    for (int c = 0; c < 128; c++) a += fc2w[c*128+t]*s6[c];
    s7[t] = lrelu(a);
    __syncthreads();
    float* ob = out + (size_t)b*6144;
    for (int o0 = 0; o0 < 6144; o0 += 512) {
        float acc[4];
        #pragma unroll
        for (int u = 0; u < 4; u++) acc[u] = fc3b[o0 + u*128 + t];
        #pragma unroll 4
        for (int c = 0; c < 128; c++) {
            float v = s7[c];
            const float* wr = fc3w + (size_t)c*6144 + o0 + t;
            #pragma unroll
            for (int u = 0; u < 4; u++) acc[u] += wr[u*128]*v;
        }
        #pragma unroll
        for (int u = 0; u < 4; u++) ob[o0 + u*128 + t] = acc[u];
    }
}

// ---------------- host ----------------
extern "C" void kernel_launch(void* const* d_in, const int* in_sizes, int n_in,
                              void* d_out, int out_size) {
    const float* x    = (const float*)d_in[0];
    const float* h1w1 = (const float*)d_in[1];
    const float* h1b1 = (const float*)d_in[2];
    const float* h1w2 = (const float*)d_in[3];
    const float* h1b2 = (const float*)d_in[4];
    const float* h1w3 = (const float*)d_in[5];
    const float* h1b3 = (const float*)d_in[6];
    const float* h2w1 = (const float*)d_in[7];
    const float* h2b1 = (const float*)d_in[8];
    const float* h2w2 = (const float*)d_in[9];
    const float* h2b2 = (const float*)d_in[10];
    const float* h3w1 = (const float*)d_in[11];
    const float* h3b1 = (const float*)d_in[12];
    const float* fc1w = (const float*)d_in[13];
    const float* fc1b = (const float*)d_in[14];
    const float* fc2w = (const float*)d_in[15];
    const float* fc2b = (const float*)d_in[16];
    const float* fc3w = (const float*)d_in[17];
    const float* fc3b = (const float*)d_in[18];
    float* out = (float*)d_out;

    cudaFuncSetAttribute(mlp2_kernel, cudaFuncAttributeMaxDynamicSharedMemorySize, MLP2_SMEM);

    dim3 dgrid(32, 32, BATCH);

    // ---- stage 1 (C=3) ----
    sq_kernel<<<2048, 256>>>(x, 3);
    dist_kernel<3><<<dgrid, 256>>>(x);
    topk_kernel<<<BN, 128>>>();
    mlp1_kernel<<<BN/8, 128>>>(x, h1w1, h1b1, h1w2, h1b2, h1w3, h1b3);

    // ---- stage 2 (C=32) ----
    void* p2; cudaGetSymbolAddress(&p2, g_x2);
    void* p3; cudaGetSymbolAddress(&p3, g_x3);
    sq_kernel<<<2048, 256>>>((const float*)p2, 32);
    dist_kernel<32><<<dgrid, 256>>>((const float*)p2);
    topk_kernel<<<BN, 128>>>();
    proj_kernel<32, 256><<<BN/4, 256>>>((const float*)p2, h2w1, h2b1);
    mlp2_kernel<<<BN/8, 256, MLP2_SMEM>>>(h2w2, h2b2);

    // ---- stage 3 (C=128) ----
    sq_kernel<<<2048, 256>>>((const float*)p3, 128);
    dist_kernel<128><<<dgrid, 256>>>((const float*)p3);
    topk_kernel<<<BN, 128>>>();
    proj_kernel<128, 128><<<BN/8, 256>>>((const float*)p3, h3w1, h3b1);
    block3_kernel<<<BN, 128>>>();

    // ---- head ----
    maxpool_kernel<<<dim3(BATCH, 16), 128>>>();
    final_kernel<<<BATCH, 128>>>(fc1w, fc1b, fc2w, fc2b, fc3w, fc3b, out);
}

// round 5
// speedup vs baseline: 1.3615x; 1.3615x over previous
#include <cuda_runtime.h>
#include <float.h>
#include <stdint.h>

#define BATCH 8
#define NPT   2048
#define KNB   16
#define BN    (BATCH*NPT)

__device__ float g_D[(size_t)BATCH*NPT*NPT];
__device__ float g_sq[BN];
__device__ int   g_idx[BN*KNB];
__device__ float g_x2[BN*32];
__device__ float g_x3[BN*128];
__device__ float g_A [BN*256];
__device__ float g_Bf[BN*256];
__device__ float g_x4[BN*128];
__device__ float g_x5p[BATCH*16*128];
__device__ float g_Xhi[BN*128];
__device__ float g_Xlo[BN*128];
__device__ float g_W2Thi[128*256];   // [n][k] row-major, k contiguous
__device__ float g_W2Tlo[128*256];

__device__ __forceinline__ float lrelu(float v) { return v >= 0.f ? v : 0.01f*v; }
__device__ __forceinline__ float tf32r(float x) {
    uint32_t u; asm("cvt.rna.tf32.f32 %0, %1;" : "=r"(u) : "f"(x));
    return __uint_as_float(u);
}

// mma.sync m16n8k8 tf32 (supported on plain compute_103 -> HMMA on sm_103)
__device__ __forceinline__ void mma8(float c[4], const uint32_t a[4], const uint32_t b[2]) {
    asm("mma.sync.aligned.m16n8k8.row.col.f32.tf32.tf32.f32 "
        "{%0,%1,%2,%3}, {%4,%5,%6,%7}, {%8,%9}, {%0,%1,%2,%3};"
        : "+f"(c[0]), "+f"(c[1]), "+f"(c[2]), "+f"(c[3])
        : "r"(a[0]), "r"(a[1]), "r"(a[2]), "r"(a[3]), "r"(b[0]), "r"(b[1]));
}

#define KP 36   // smem K stride (pad): bank = 4g+t, conflict-free

// warp GEMM over one K=32 chunk: 3-pass tf32 split, warp tile 32x32
__device__ __forceinline__ void chunk_gemm(
        const float* __restrict__ Ahi, const float* __restrict__ Alo,
        const float* __restrict__ Bhi, const float* __restrict__ Blo,
        float (&c)[2][4][4], int rb, int cb, int g, int tq) {
    #pragma unroll
    for (int ks = 0; ks < 4; ks++) {
        int k0 = ks*8;
        uint32_t aH[2][4], aL[2][4], bH[4][2], bL[4][2];
        #pragma unroll
        for (int mt = 0; mt < 2; mt++) {
            int base = (rb + mt*16 + g)*KP + k0 + tq;
            aH[mt][0] = __float_as_uint(Ahi[base]);
            aH[mt][1] = __float_as_uint(Ahi[base + 8*KP]);
            aH[mt][2] = __float_as_uint(Ahi[base + 4]);
            aH[mt][3] = __float_as_uint(Ahi[base + 8*KP + 4]);
            aL[mt][0] = __float_as_uint(Alo[base]);
            aL[mt][1] = __float_as_uint(Alo[base + 8*KP]);
            aL[mt][2] = __float_as_uint(Alo[base + 4]);
            aL[mt][3] = __float_as_uint(Alo[base + 8*KP + 4]);
        }
        #pragma unroll
        for (int nt = 0; nt < 4; nt++) {
            int base = (cb + nt*8 + g)*KP + k0 + tq;
            bH[nt][0] = __float_as_uint(Bhi[base]);
            bH[nt][1] = __float_as_uint(Bhi[base + 4]);
            bL[nt][0] = __float_as_uint(Blo[base]);
            bL[nt][1] = __float_as_uint(Blo[base + 4]);
        }
        #pragma unroll
        for (int mt = 0; mt < 2; mt++)
            #pragma unroll
            for (int nt = 0; nt < 4; nt++) {
                mma8(c[mt][nt], aH[mt], bH[nt]);
                mma8(c[mt][nt], aL[mt], bH[nt]);
                mma8(c[mt][nt], aH[mt], bL[nt]);
            }
    }
}

// ======== squared norms ========
__global__ void sq_kernel(const float* __restrict__ X, int C) {
    int gw = (blockIdx.x*blockDim.x + threadIdx.x) >> 5, lane = threadIdx.x & 31;
    if (gw >= BN) return;
    const float* r = X + (size_t)gw*C;
    float acc = 0.f;
    for (int c = lane; c < C; c += 32) { float v = r[c]; acc += v*v; }
    #pragma unroll
    for (int o = 16; o; o >>= 1) acc += __shfl_xor_sync(0xffffffffu, acc, o);
    if (lane == 0) g_sq[gw] = acc;
}

// ======== tf32 hi/lo split prep ========
__global__ void split_kernel(const float* __restrict__ X, int n) {
    int e = blockIdx.x*256 + threadIdx.x;
    if (e >= n) return;
    float x = X[e];
    float hi = tf32r(x);
    g_Xhi[e] = hi;
    g_Xlo[e] = tf32r(x - hi);
}

__global__ void prepw2_kernel(const float* __restrict__ W2) {
    int e = blockIdx.x*256 + threadIdx.x;   // 32768 = 256x128
    if (e >= 32768) return;
    int k = e >> 7, n = e & 127;
    float x = W2[e];
    float hi = tf32r(x);
    g_W2Thi[n*256 + k] = hi;
    g_W2Tlo[n*256 + k] = tf32r(x - hi);
}

// ======== dist C=3 (FFMA) ========
__global__ __launch_bounds__(256) void dist3_kernel(const float* __restrict__ X) {
    __shared__ float As[3][65], Bs[3][65];
    int b = blockIdx.z, i0 = blockIdx.y*64, j0 = blockIdx.x*64;
    const float* Xb = X + (size_t)b*NPT*3;
    int t = threadIdx.x, tx = t & 15, ty = t >> 4;
    for (int e = t; e < 192; e += 256) {
        int r = e/3, c = e%3;
        As[c][r] = Xb[(size_t)(i0+r)*3 + c];
        Bs[c][r] = Xb[(size_t)(j0+r)*3 + c];
    }
    __syncthreads();
    float acc[4][4] = {};
    #pragma unroll
    for (int c = 0; c < 3; c++) {
        float av[4], bv[4];
        #pragma unroll
        for (int u = 0; u < 4; u++) { av[u] = As[c][ty*4+u]; bv[u] = Bs[c][tx*4+u]; }
        #pragma unroll
        for (int i = 0; i < 4; i++)
            #pragma unroll
            for (int j = 0; j < 4; j++) acc[i][j] += av[i]*bv[j];
    }
    const float* sqb = g_sq + b*NPT;
    float* Db = g_D + (size_t)b*NPT*NPT;
    int j = j0 + tx*4;
    float s0=sqb[j], s1=sqb[j+1], s2=sqb[j+2], s3=sqb[j+3];
    #pragma unroll
    for (int i = 0; i < 4; i++) {
        int ii = i0 + ty*4 + i; float si = sqb[ii];
        float4 o = { si+s0-2.f*acc[i][0], si+s1-2.f*acc[i][1], si+s2-2.f*acc[i][2], si+s3-2.f*acc[i][3] };
        *(float4*)(Db + (size_t)ii*NPT + j) = o;
    }
}

// ======== dist via mma.sync tf32 (C=32,128): 128x128 tile, 16 warps ========
#define DIST_SM (18688*4)
template<int C>
__global__ __launch_bounds__(512) void dist_mma() {
    extern __shared__ __align__(16) float sm[];
    float* Ahi = sm;           float* Alo = sm + 4608;
    float* Bhi = sm + 9216;    float* Blo = sm + 13824;
    float* sqi = sm + 18432;   float* sqj = sm + 18560;
    int t = threadIdx.x, wid = t >> 5, lane = t & 31;
    int g = lane >> 2, tq = lane & 3;
    int rb = (wid & 3)*32, cb = (wid >> 2)*32;
    int b = blockIdx.z, i0 = blockIdx.y*128, j0 = blockIdx.x*128;
    if (t < 128) { sqi[t] = g_sq[b*NPT + i0 + t]; sqj[t] = g_sq[b*NPT + j0 + t]; }
    float c[2][4][4] = {};
    const float* XiH = g_Xhi + (size_t)(b*NPT + i0)*C;
    const float* XiL = g_Xlo + (size_t)(b*NPT + i0)*C;
    const float* XjH = g_Xhi + (size_t)(b*NPT + j0)*C;
    const float* XjL = g_Xlo + (size_t)(b*NPT + j0)*C;
    #pragma unroll 1
    for (int ch = 0; ch < C/32; ch++) {
        __syncthreads();
        for (int e = t; e < 4096; e += 512) {
            int arr = e >> 10, le = e & 1023;
            int row = le >> 3, q = le & 7;
            const float* src = (arr == 0) ? XiH : (arr == 1) ? XiL : (arr == 2) ? XjH : XjL;
            float* dst = (arr == 0) ? Ahi : (arr == 1) ? Alo : (arr == 2) ? Bhi : Blo;
            *(float4*)(dst + row*KP + q*4) = *(const float4*)(src + (size_t)row*C + ch*32 + q*4);
        }
        __syncthreads();
        chunk_gemm(Ahi, Alo, Bhi, Blo, c, rb, cb, g, tq);
    }
    float* Db = g_D + (size_t)b*NPT*NPT;
    #pragma unroll
    for (int mt = 0; mt < 2; mt++) {
        int r0 = rb + mt*16 + g;
        float si0 = sqi[r0], si1 = sqi[r0 + 8];
        #pragma unroll
        for (int nt = 0; nt < 4; nt++) {
            int cl = cb + nt*8 + 2*tq;
            float sj0 = sqj[cl], sj1 = sqj[cl + 1];
            float2 v0 = { si0 + sj0 - 2.f*c[mt][nt][0], si0 + sj1 - 2.f*c[mt][nt][1] };
            float2 v1 = { si1 + sj0 - 2.f*c[mt][nt][2], si1 + sj1 - 2.f*c[mt][nt][3] };
            *(float2*)(Db + (size_t)(i0 + r0)*NPT + j0 + cl) = v0;
            *(float2*)(Db + (size_t)(i0 + r0 + 8)*NPT + j0 + cl) = v1;
        }
    }
}

// ======== top-16 ========
#define PHYS(s) ((s) + ((s) >> 5))
__global__ __launch_bounds__(128) void topk_kernel() {
    __shared__ float sd[NPT + 64];
    __shared__ float rbest[4]; __shared__ int ribest[4];
    int row = blockIdx.x, t = threadIdx.x;
    const float* Dr = g_D + (size_t)row * NPT;
    for (int s = t; s < NPT; s += 128) sd[PHYS(s)] = Dr[s];
    __syncthreads();
    for (int it = 0; it < KNB; it++) {
        float best = FLT_MAX; int bi = NPT;
        for (int s = t; s < NPT; s += 128) {
            float v = sd[PHYS(s)];
            if (v < best) { best = v; bi = s; }
        }
        #pragma unroll
        for (int o = 16; o; o >>= 1) {
            float ov = __shfl_down_sync(0xffffffffu, best, o);
            int   oi = __shfl_down_sync(0xffffffffu, bi, o);
            if (ov < best || (ov == best && oi < bi)) { best = ov; bi = oi; }
        }
        if ((t & 31) == 0) { rbest[t>>5] = best; ribest[t>>5] = bi; }
        __syncthreads();
        if (t == 0) {
            #pragma unroll
            for (int w = 1; w < 4; w++)
                if (rbest[w] < best || (rbest[w] == best && ribest[w] < bi)) { best = rbest[w]; bi = ribest[w]; }
            g_idx[row*KNB + it] = bi;
            sd[PHYS(bi)] = FLT_MAX;
        }
        __syncthreads();
    }
}

// ======== block 1 edge MLP (6->16->64->32, sum K) ========
__global__ __launch_bounds__(128) void mlp1_kernel(
        const float* __restrict__ x,
        const float* __restrict__ w1, const float* __restrict__ b1,
        const float* __restrict__ w2, const float* __restrict__ b2,
        const float* __restrict__ w3, const float* __restrict__ b3) {
    __shared__ float s1[96], sb1[16], s2[1024], sb2[64], s3[2048], sb3[32];
    int t = threadIdx.x;
    if (t < 96) s1[t] = w1[t];
    if (t < 16) sb1[t] = b1[t];
    for (int e = t; e < 1024; e += 128) s2[e] = w2[e];
    if (t < 64) sb2[t] = b2[t];
    for (int e = t; e < 2048; e += 128) s3[e] = w3[e];
    if (t < 32) sb3[t] = b3[t];
    __syncthreads();
    int k = t & 15, lp = t >> 4;
    int p = blockIdx.x * 8 + lp, b = p >> 11;
    int j = g_idx[p*KNB + k];
    const float* xc = x + (size_t)p*3;
    const float* xn = x + (size_t)(b*NPT + j)*3;
    float in[6] = { xc[0], xc[1], xc[2], xn[0], xn[1], xn[2] };
    float h16[16];
    #pragma unroll
    for (int o = 0; o < 16; o++) {
        float a = sb1[o];
        #pragma unroll
        for (int c = 0; c < 6; c++) a += s1[c*16+o]*in[c];
        h16[o] = lrelu(a);
    }
    float h64[64];
    #pragma unroll
    for (int o = 0; o < 64; o++) {
        float a = sb2[o];
        #pragma unroll
        for (int c = 0; c < 16; c++) a += s2[c*64+o]*h16[c];
        h64[o] = lrelu(a);
    }
    float h32[32];
    #pragma unroll
    for (int o = 0; o < 32; o++) {
        float a = sb3[o];
        #pragma unroll
        for (int c = 0; c < 64; c++) a += s3[c*32+o]*h64[c];
        h32[o] = lrelu(a);
    }
    #pragma unroll
    for (int c = 0; c < 32; c++) {
        #pragma unroll
        for (int o = 8; o; o >>= 1) h32[c] += __shfl_xor_sync(0xffffffffu, h32[c], o);
    }
    if (k == 0) {
        float* outp = g_x2 + (size_t)p*32;
        #pragma unroll
        for (int c = 0; c < 32; c++) outp[c] = h32[c];
    }
}

// ======== factored layer-1 projections ========
template<int CIN, int COUT>
__global__ __launch_bounds__(256) void proj_kernel(
        const float* __restrict__ X, const float* __restrict__ W,
        const float* __restrict__ bias) {
    constexpr int OG = COUT/4;
    constexpr int R  = 256/OG;
    __shared__ float sin[R][CIN];
    int t = threadIdx.x, p0 = blockIdx.x * R;
    for (int e = t; e < R*CIN; e += 256) sin[e/CIN][e%CIN] = X[(size_t)p0*CIN + e];
    __syncthreads();
    int og = t % OG, r = t / OG;
    float4 aa = {0,0,0,0}, bb = {0,0,0,0};
    #pragma unroll 4
    for (int c = 0; c < CIN; c++) {
        float v = sin[r][c];
        float4 wa = *(const float4*)(W + (size_t)c*COUT + og*4);
        float4 wb = *(const float4*)(W + (size_t)(CIN+c)*COUT + og*4);
        aa.x += wa.x*v; aa.y += wa.y*v; aa.z += wa.z*v; aa.w += wa.w*v;
        bb.x += wb.x*v; bb.y += wb.y*v; bb.z += wb.z*v; bb.w += wb.w*v;
    }
    float4 b4 = *(const float4*)(bias + og*4);
    aa.x += b4.x; aa.y += b4.y; aa.z += b4.z; aa.w += b4.w;
    *(float4*)(g_A  + (size_t)(p0+r)*COUT + og*4) = aa;
    *(float4*)(g_Bf + (size_t)(p0+r)*COUT + og*4) = bb;
}

// ======== block 2 layer-2 via mma.sync: 128 edges x 128 outs, K=256 ========
#define MLP2_SM (18688*4)
__global__ __launch_bounds__(512) void mlp2_mma(const float* __restrict__ b2) {
    extern __shared__ __align__(16) float sm[];
    float* Ahi = sm;           float* Alo = sm + 4608;
    float* Bhi = sm + 9216;    float* Blo = sm + 13824;
    float* stage = sm;                     // reused after GEMM: 128*132 = 16896 < 18432
    float* b2s = sm + 18432;
    int*   rowsrc = (int*)(sm + 18560);
    int t = threadIdx.x, wid = t >> 5, lane = t & 31;
    int g = lane >> 2, tq = lane & 3;
    int rb = (wid & 3)*32, cb = (wid >> 2)*32;
    int p0 = blockIdx.x*8, b = p0 >> 11;
    if (t < 128) {
        b2s[t] = b2[t];
        rowsrc[t] = b*NPT + g_idx[(p0 + (t>>4))*KNB + (t & 15)];
    }
    float c[2][4][4] = {};
    #pragma unroll 1
    for (int ch = 0; ch < 8; ch++) {
        __syncthreads();
        // H tile: gather + factored-add + lrelu + tf32 split
        for (int e = t; e < 4096; e += 512) {
            int row = e >> 5, kq = e & 31, ci = ch*32 + kq;
            float v = lrelu(g_A[(size_t)(p0 + (row>>4))*256 + ci] + g_Bf[(size_t)rowsrc[row]*256 + ci]);
            float hi = tf32r(v);
            Ahi[row*KP + kq] = hi;
            Alo[row*KP + kq] = tf32r(v - hi);
        }
        // W tile (pre-split, k-contiguous)
        for (int e = t; e < 2048; e += 512) {
            int arr = e >> 10, le = e & 1023;
            int n = le >> 3, q = le & 7;
            const float* src = arr ? g_W2Tlo : g_W2Thi;
            float* dst = arr ? Blo : Bhi;
            *(float4*)(dst + n*KP + q*4) = *(const float4*)(src + n*256 + ch*32 + q*4);
        }
        __syncthreads();
        chunk_gemm(Ahi, Alo, Bhi, Blo, c, rb, cb, g, tq);
    }
    __syncthreads();   // all warps done with A/B smem before stage reuse
    #pragma unroll
    for (int mt = 0; mt < 2; mt++) {
        int r0 = rb + mt*16 + g;
        #pragma unroll
        for (int nt = 0; nt < 4; nt++) {
            int cl = cb + nt*8 + 2*tq;
            float bb0 = b2s[cl], bb1 = b2s[cl + 1];
            float2 v0 = { lrelu(c[mt][nt][0] + bb0), lrelu(c[mt][nt][1] + bb1) };
            float2 v1 = { lrelu(c[mt][nt][2] + bb0), lrelu(c[mt][nt][3] + bb1) };
            *(float2*)(stage + r0*132 + cl) = v0;
            *(float2*)(stage + (r0 + 8)*132 + cl) = v1;
        }
    }
    __syncthreads();
    for (int o = t; o < 1024; o += 512) {
        int pl = o >> 7, cl = o & 127;
        const float* sp = stage + (pl*16)*132 + cl;
        float s = 0.f;
        #pragma unroll
        for (int kk = 0; kk < 16; kk++) s += sp[kk*132];
        g_x3[(size_t)(p0 + pl)*128 + cl] = s;
    }
}

// ======== block 3 (fully factored) ========
__global__ __launch_bounds__(128) void block3_kernel() {
    __shared__ int idxs[KNB];
    int p = blockIdx.x, t = threadIdx.x, b = p >> 11;
    if (t < KNB) idxs[t] = g_idx[p*KNB + t];
    __syncthreads();
    float a = g_A[(size_t)p*128 + t];
    float acc = 0.f;
    #pragma unroll
    for (int k = 0; k < KNB; k++)
        acc += lrelu(a + g_Bf[(size_t)(b*NPT + idxs[k])*128 + t]);
    g_x4[(size_t)p*128 + t] = acc;
}

// ======== max pool + head ========
__global__ __launch_bounds__(128) void maxpool_kernel() {
    int b = blockIdx.x, seg = blockIdx.y, t = threadIdx.x;
    const float* base = g_x4 + ((size_t)b*NPT + seg*128)*128 + t;
    float m = -FLT_MAX;
    #pragma unroll 8
    for (int r = 0; r < 128; r++) m = fmaxf(m, base[(size_t)r*128]);
    g_x5p[(b*16 + seg)*128 + t] = m;
}

__global__ __launch_bounds__(128) void final_kernel(
        const float* __restrict__ fc1w, const float* __restrict__ fc1b,
        const float* __restrict__ fc2w, const float* __restrict__ fc2b,
        const float* __restrict__ fc3w, const float* __restrict__ fc3b,
        float* __restrict__ out) {
    __shared__ float s5[128], s6[128], s7[128];
    int b = blockIdx.x, t = threadIdx.x;
    float m = -FLT_MAX;
    #pragma unroll
    for (int s = 0; s < 16; s++) m = fmaxf(m, g_x5p[(b*16+s)*128 + t]);
    s5[t] = m;
    __syncthreads();
    float a = fc1b[t];
    #pragma unroll 8
    for (int c = 0; c < 128; c++) a += fc1w[c*128+t]*s5[c];
    s6[t] = lrelu(a);
    __syncthreads();
    a = fc2b[t];
    #pragma unroll 8
    for (int c = 0; c < 128; c++) a += fc2w[c*128+t]*s6[c];
    s7[t] = lrelu(a);
    __syncthreads();
    float* ob = out + (size_t)b*6144;
    for (int o0 = 0; o0 < 6144; o0 += 512) {
        float acc[4];
        #pragma unroll
        for (int u = 0; u < 4; u++) acc[u] = fc3b[o0 + u*128 + t];
        #pragma unroll 4
        for (int c = 0; c < 128; c++) {
            float v = s7[c];
            const float* wr = fc3w + (size_t)c*6144 + o0 + t;
            #pragma unroll
            for (int u = 0; u < 4; u++) acc[u] += wr[u*128]*v;
        }
        #pragma unroll
        for (int u = 0; u < 4; u++) ob[o0 + u*128 + t] = acc[u];
    }
}

// ======== host ========
extern "C" void kernel_launch(void* const* d_in, const int* in_sizes, int n_in,
                              void* d_out, int out_size) {
    const float* x    = (const float*)d_in[0];
    const float* h1w1 = (const float*)d_in[1];
    const float* h1b1 = (const float*)d_in[2];
    const float* h1w2 = (const float*)d_in[3];
    const float* h1b2 = (const float*)d_in[4];
    const float* h1w3 = (const float*)d_in[5];
    const float* h1b3 = (const float*)d_in[6];
    const float* h2w1 = (const float*)d_in[7];
    const float* h2b1 = (const float*)d_in[8];
    const float* h2w2 = (const float*)d_in[9];
    const float* h2b2 = (const float*)d_in[10];
    const float* h3w1 = (const float*)d_in[11];
    const float* h3b1 = (const float*)d_in[12];
    const float* fc1w = (const float*)d_in[13];
    const float* fc1b = (const float*)d_in[14];
    const float* fc2w = (const float*)d_in[15];
    const float* fc2b = (const float*)d_in[16];
    const float* fc3w = (const float*)d_in[17];
    const float* fc3b = (const float*)d_in[18];
    float* out = (float*)d_out;

    cudaFuncSetAttribute(dist_mma<32>,  cudaFuncAttributeMaxDynamicSharedMemorySize, DIST_SM);
    cudaFuncSetAttribute(dist_mma<128>, cudaFuncAttributeMaxDynamicSharedMemorySize, DIST_SM);
    cudaFuncSetAttribute(mlp2_mma,      cudaFuncAttributeMaxDynamicSharedMemorySize, MLP2_SM);

    void* p2; cudaGetSymbolAddress(&p2, g_x2);
    void* p3; cudaGetSymbolAddress(&p3, g_x3);
    dim3 d3grid(32, 32, BATCH);
    dim3 tcgrid(16, 16, BATCH);

    // stage 1 (C=3)
    sq_kernel<<<2048, 256>>>(x, 3);
    dist3_kernel<<<d3grid, 256>>>(x);
    topk_kernel<<<BN, 128>>>();
    mlp1_kernel<<<BN/8, 128>>>(x, h1w1, h1b1, h1w2, h1b2, h1w3, h1b3);

    // stage 2 (C=32)
    sq_kernel<<<2048, 256>>>((const float*)p2, 32);
    split_kernel<<<BN*32/256, 256>>>((const float*)p2, BN*32);
    dist_mma<32><<<tcgrid, 512, DIST_SM>>>();
    topk_kernel<<<BN, 128>>>();
    proj_kernel<32, 256><<<BN/4, 256>>>((const float*)p2, h2w1, h2b1);
    prepw2_kernel<<<128, 256>>>(h2w2);
    mlp2_mma<<<BN/8, 512, MLP2_SM>>>(h2b2);

    // stage 3 (C=128)
    sq_kernel<<<2048, 256>>>((const float*)p3, 128);
    split_kernel<<<BN*128/256, 256>>>((const float*)p3, BN*128);
    dist_mma<128><<<tcgrid, 512, DIST_SM>>>();
    topk_kernel<<<BN, 128>>>();
    proj_kernel<128, 128><<<BN/8, 256>>>((const float*)p3, h3w1, h3b1);
    block3_kernel<<<BN, 128>>>();

    // head
    maxpool_kernel<<<dim3(BATCH, 16), 128>>>();
    final_kernel<<<BATCH, 128>>>(fc1w, fc1b, fc2w, fc2b, fc3w, fc3b, out);
}

// round 7
// speedup vs baseline: 2.1425x; 1.5736x over previous
#include <cuda_runtime.h>
#include <float.h>
#include <stdint.h>

#define BATCH 8
#define NPT   2048
#define KNB   16
#define BN    (BATCH*NPT)

__device__ float g_D[(size_t)BATCH*NPT*NPT];
__device__ float g_sq[BN];
__device__ int   g_idx[BN*KNB];
__device__ float g_x2[BN*32];
__device__ float g_x3[BN*128];
__device__ float g_A [BN*256];
__device__ float g_Bf[BN*256];
__device__ float g_x4[BN*128];
__device__ float g_x5p[BATCH*16*128];
__device__ float g_Xhi[BN*128];
__device__ float g_Xlo[BN*128];
__device__ float g_W2Thi[128*256];   // [n][k], k contiguous
__device__ float g_W2Tlo[128*256];

__device__ __forceinline__ float lrelu(float v) { return v >= 0.f ? v : 0.01f*v; }
__device__ __forceinline__ float tf32r(float x) {
    uint32_t u; asm("cvt.rna.tf32.f32 %0, %1;" : "=r"(u) : "f"(x));
    return __uint_as_float(u);
}
__device__ __forceinline__ uint32_t smem_u32(const void* p) {
    uint32_t a;
    asm("{ .reg .u64 t; cvta.to.shared.u64 t, %1; cvt.u32.u64 %0, t; }" : "=r"(a) : "l"(p));
    return a;
}
__device__ __forceinline__ void cpa16(uint32_t saddr, const void* g) {
    asm volatile("cp.async.cg.shared.global [%0], [%1], 16;" :: "r"(saddr), "l"(g));
}
#define CPA_COMMIT() asm volatile("cp.async.commit_group;" ::: "memory")
#define CPA_WAIT1()  asm volatile("cp.async.wait_group 1;" ::: "memory")
#define CPA_WAIT0()  asm volatile("cp.async.wait_group 0;" ::: "memory")

__device__ __forceinline__ void mma8(float c[4], const uint32_t a[4], const uint32_t b[2]) {
    asm("mma.sync.aligned.m16n8k8.row.col.f32.tf32.tf32.f32 "
        "{%0,%1,%2,%3}, {%4,%5,%6,%7}, {%8,%9}, {%0,%1,%2,%3};"
        : "+f"(c[0]), "+f"(c[1]), "+f"(c[2]), "+f"(c[3])
        : "r"(a[0]), "r"(a[1]), "r"(a[2]), "r"(a[3]), "r"(b[0]), "r"(b[1]));
}

// XOR-swizzled index within a 128-row x 32-float K-major tile (conflict-free)
__device__ __forceinline__ int swidx(int row, int kq) {
    return row*32 + (kq ^ ((row & 7) << 2));
}

// warp GEMM over one K=32 chunk: 3-pass tf32 split, warp tile 32x32
// A: hi at +0, lo at +4096 ; B likewise
__device__ __forceinline__ void chunk_gemm(const float* __restrict__ A,
                                           const float* __restrict__ B,
                                           float (&c)[2][4][4],
                                           int rb, int cb, int g, int tq) {
    #pragma unroll
    for (int ks = 0; ks < 4; ks++) {
        int k0 = ks*8;
        uint32_t aH[2][4], aL[2][4], bH[4][2], bL[4][2];
        #pragma unroll
        for (int mt = 0; mt < 2; mt++) {
            int r0 = rb + mt*16 + g;
            int i00 = swidx(r0,   k0+tq), i01 = swidx(r0,   k0+tq+4);
            int i10 = swidx(r0+8, k0+tq), i11 = swidx(r0+8, k0+tq+4);
            aH[mt][0]=__float_as_uint(A[i00]); aH[mt][1]=__float_as_uint(A[i10]);
            aH[mt][2]=__float_as_uint(A[i01]); aH[mt][3]=__float_as_uint(A[i11]);
            aL[mt][0]=__float_as_uint(A[4096+i00]); aL[mt][1]=__float_as_uint(A[4096+i10]);
            aL[mt][2]=__float_as_uint(A[4096+i01]); aL[mt][3]=__float_as_uint(A[4096+i11]);
        }
        #pragma unroll
        for (int nt = 0; nt < 4; nt++) {
            int n0 = cb + nt*8 + g;
            int j0i = swidx(n0, k0+tq), j1i = swidx(n0, k0+tq+4);
            bH[nt][0]=__float_as_uint(B[j0i]); bH[nt][1]=__float_as_uint(B[j1i]);
            bL[nt][0]=__float_as_uint(B[4096+j0i]); bL[nt][1]=__float_as_uint(B[4096+j1i]);
        }
        #pragma unroll
        for (int mt = 0; mt < 2; mt++)
            #pragma unroll
            for (int nt = 0; nt < 4; nt++) {
                mma8(c[mt][nt], aH[mt], bH[nt]);
                mma8(c[mt][nt], aL[mt], bH[nt]);
                mma8(c[mt][nt], aH[mt], bL[nt]);
            }
    }
}

// ======== squared norms (C=3 path) ========
__global__ void sq_kernel(const float* __restrict__ X, int C) {
    int gw = (blockIdx.x*blockDim.x + threadIdx.x) >> 5, lane = threadIdx.x & 31;
    if (gw >= BN) return;
    const float* r = X + (size_t)gw*C;
    float acc = 0.f;
    for (int c = lane; c < C; c += 32) { float v = r[c]; acc += v*v; }
    #pragma unroll
    for (int o = 16; o; o >>= 1) acc += __shfl_xor_sync(0xffffffffu, acc, o);
    if (lane == 0) g_sq[gw] = acc;
}

// ======== fused sq + tf32 split (warp per point) ========
template<int C>
__global__ void prep_kernel(const float* __restrict__ X) {
    int gw = (blockIdx.x*blockDim.x + threadIdx.x) >> 5, lane = threadIdx.x & 31;
    if (gw >= BN) return;
    const float* r = X + (size_t)gw*C;
    float acc = 0.f;
    #pragma unroll
    for (int c = lane; c < C; c += 32) {
        float v = r[c];
        acc += v*v;
        float hi = tf32r(v);
        g_Xhi[(size_t)gw*C + c] = hi;
        g_Xlo[(size_t)gw*C + c] = tf32r(v - hi);
    }
    #pragma unroll
    for (int o = 16; o; o >>= 1) acc += __shfl_xor_sync(0xffffffffu, acc, o);
    if (lane == 0) g_sq[gw] = acc;
}

__global__ __launch_bounds__(256) void prepw2_kernel(const float* __restrict__ W2) {
    int e = blockIdx.x*256 + threadIdx.x;   // 32768 = 256x128
    if (e >= 32768) return;
    int k = e >> 7, n = e & 127;
    float x = W2[e];
    float hi = tf32r(x);
    g_W2Thi[n*256 + k] = hi;
    g_W2Tlo[n*256 + k] = tf32r(x - hi);
}

// ======== dist C=3 (FFMA) ========
__global__ __launch_bounds__(256) void dist3_kernel(const float* __restrict__ X) {
    __shared__ float As[3][65], Bs[3][65];
    int b = blockIdx.z, i0 = blockIdx.y*64, j0 = blockIdx.x*64;
    const float* Xb = X + (size_t)b*NPT*3;
    int t = threadIdx.x, tx = t & 15, ty = t >> 4;
    for (int e = t; e < 192; e += 256) {
        int r = e/3, c = e%3;
        As[c][r] = Xb[(size_t)(i0+r)*3 + c];
        Bs[c][r] = Xb[(size_t)(j0+r)*3 + c];
    }
    __syncthreads();
    float acc[4][4] = {};
    #pragma unroll
    for (int c = 0; c < 3; c++) {
        float av[4], bv[4];
        #pragma unroll
        for (int u = 0; u < 4; u++) { av[u] = As[c][ty*4+u]; bv[u] = Bs[c][tx*4+u]; }
        #pragma unroll
        for (int i = 0; i < 4; i++)
            #pragma unroll
            for (int j = 0; j < 4; j++) acc[i][j] += av[i]*bv[j];
    }
    const float* sqb = g_sq + b*NPT;
    float* Db = g_D + (size_t)b*NPT*NPT;
    int j = j0 + tx*4;
    float s0=sqb[j], s1=sqb[j+1], s2=sqb[j+2], s3=sqb[j+3];
    #pragma unroll
    for (int i = 0; i < 4; i++) {
        int ii = i0 + ty*4 + i; float si = sqb[ii];
        float4 o = { si+s0-2.f*acc[i][0], si+s1-2.f*acc[i][1], si+s2-2.f*acc[i][2], si+s3-2.f*acc[i][3] };
        *(float4*)(Db + (size_t)ii*NPT + j) = o;
    }
}

// ======== dist via mma.sync, triangular grid + symmetric write ========
// smem floats: buf 2x16384 (Ahi,Alo,Bhi,Blo x4096 each) | sqi 128 | sqj 128 ; stage reuses buf
#define DIST_SM (33024*4)
template<int C>
__global__ __launch_bounds__(512) void dist_mma() {
    extern __shared__ __align__(16) float sm[];
    float* sqi = sm + 32768; float* sqj = sm + 32896;
    int t = threadIdx.x, wid = t >> 5, lane = t & 31;
    int g = lane >> 2, tq = lane & 3;
    int rb = (wid & 3)*32, cb = (wid >> 2)*32;
    int b = blockIdx.z;
    int L = blockIdx.x, bi = 0;
    while (L >= 16 - bi) { L -= 16 - bi; bi++; }
    int bj = bi + L;
    int i0 = bi*128, j0 = bj*128;
    if (t < 128) { sqi[t] = g_sq[b*NPT + i0 + t]; sqj[t] = g_sq[b*NPT + j0 + t]; }
    const float* XiH = g_Xhi + (size_t)(b*NPT + i0)*C;
    const float* XiL = g_Xlo + (size_t)(b*NPT + i0)*C;
    const float* XjH = g_Xhi + (size_t)(b*NPT + j0)*C;
    const float* XjL = g_Xlo + (size_t)(b*NPT + j0)*C;
    uint32_t smb = smem_u32(sm);
    constexpr int NC = C/32;

    // prefetch chunk into buffer set bb
    auto prefetch = [&](int ch, int bb) {
        uint32_t base = smb + (uint32_t)bb*16384u*4u;
        for (int e = t; e < 4096; e += 512) {
            int arr = e >> 10, le = e & 1023, row = le >> 3, q = le & 7;
            const float* src = (arr == 0) ? XiH : (arr == 1) ? XiL : (arr == 2) ? XjH : XjL;
            uint32_t dst = base + (uint32_t)(arr*4096 + row*32 + 4*(q ^ (row & 7)))*4u;
            cpa16(dst, src + (size_t)row*C + ch*32 + q*4);
        }
        CPA_COMMIT();
    };

    float c[2][4][4] = {};
    prefetch(0, 0);
    #pragma unroll 1
    for (int ch = 0; ch < NC; ch++) {
        int cur = ch & 1;
        if (ch + 1 < NC) { prefetch(ch + 1, cur ^ 1); CPA_WAIT1(); }
        else             { CPA_WAIT0(); }
        __syncthreads();
        const float* A = sm + cur*16384;
        chunk_gemm(A, A + 8192, c, rb, cb, g, tq);
        __syncthreads();
    }

    // stage (i-major), coalesced dump
    float* stage = sm;
    #pragma unroll
    for (int mt = 0; mt < 2; mt++) {
        int r0 = rb + mt*16 + g;
        float si0 = sqi[r0], si1 = sqi[r0 + 8];
        #pragma unroll
        for (int nt = 0; nt < 4; nt++) {
            int cl = cb + nt*8 + 2*tq;
            float sj0 = sqj[cl], sj1 = sqj[cl + 1];
            stage[r0*132 + cl]     = si0 + sj0 - 2.f*c[mt][nt][0];
            stage[r0*132 + cl + 1] = si0 + sj1 - 2.f*c[mt][nt][1];
            stage[(r0+8)*132 + cl]     = si1 + sj0 - 2.f*c[mt][nt][2];
            stage[(r0+8)*132 + cl + 1] = si1 + sj1 - 2.f*c[mt][nt][3];
        }
    }
    __syncthreads();
    float* Db = g_D + (size_t)b*NPT*NPT;
    for (int e = t; e < 4096; e += 512) {
        int r = e >> 5, q = e & 31;
        float4 v = *(const float4*)(stage + r*132 + q*4);
        *(float4*)(Db + (size_t)(i0 + r)*NPT + j0 + q*4) = v;
    }
    if (bi != bj) {
        __syncthreads();
        // transposed stage from live fragments
        #pragma unroll
        for (int mt = 0; mt < 2; mt++) {
            int r0 = rb + mt*16 + g;
            float si0 = sqi[r0], si1 = sqi[r0 + 8];
            #pragma unroll
            for (int nt = 0; nt < 4; nt++) {
                int cl = cb + nt*8 + 2*tq;
                float sj0 = sqj[cl], sj1 = sqj[cl + 1];
                stage[cl*132 + r0]     = si0 + sj0 - 2.f*c[mt][nt][0];
                stage[(cl+1)*132 + r0] = si0 + sj1 - 2.f*c[mt][nt][1];
                stage[cl*132 + r0 + 8]     = si1 + sj0 - 2.f*c[mt][nt][2];
                stage[(cl+1)*132 + r0 + 8] = si1 + sj1 - 2.f*c[mt][nt][3];
            }
        }
        __syncthreads();
        for (int e = t; e < 4096; e += 512) {
            int r = e >> 5, q = e & 31;
            float4 v = *(const float4*)(stage + r*132 + q*4);
            *(float4*)(Db + (size_t)(j0 + r)*NPT + i0 + q*4) = v;
        }
    }
}

// ======== top-16 ========
#define PHYS(s) ((s) + ((s) >> 5))
__global__ __launch_bounds__(128) void topk_kernel() {
    __shared__ float sd[NPT + 64];
    __shared__ float rbest[4]; __shared__ int ribest[4];
    int row = blockIdx.x, t = threadIdx.x;
    const float* Dr = g_D + (size_t)row * NPT;
    for (int s = t; s < NPT; s += 128) sd[PHYS(s)] = Dr[s];
    __syncthreads();
    for (int it = 0; it < KNB; it++) {
        float best = FLT_MAX; int bi = NPT;
        for (int s = t; s < NPT; s += 128) {
            float v = sd[PHYS(s)];
            if (v < best) { best = v; bi = s; }
        }
        #pragma unroll
        for (int o = 16; o; o >>= 1) {
            float ov = __shfl_down_sync(0xffffffffu, best, o);
            int   oi = __shfl_down_sync(0xffffffffu, bi, o);
            if (ov < best || (ov == best && oi < bi)) { best = ov; bi = oi; }
        }
        if ((t & 31) == 0) { rbest[t>>5] = best; ribest[t>>5] = bi; }
        __syncthreads();
        if (t == 0) {
            #pragma unroll
            for (int w = 1; w < 4; w++)
                if (rbest[w] < best || (rbest[w] == best && ribest[w] < bi)) { best = rbest[w]; bi = ribest[w]; }
            g_idx[row*KNB + it] = bi;
            sd[PHYS(bi)] = FLT_MAX;
        }
        __syncthreads();
    }
}

// ======== block 1 edge MLP, float4 weight loads ========
__global__ __launch_bounds__(128) void mlp1_kernel(
        const float* __restrict__ x,
        const float* __restrict__ w1, const float* __restrict__ b1,
        const float* __restrict__ w2, const float* __restrict__ b2,
        const float* __restrict__ w3, const float* __restrict__ b3) {
    __shared__ float s1[96], sb1[16], s2[1024], sb2[64], s3[2048], sb3[32];
    int t = threadIdx.x;
    if (t < 96) s1[t] = w1[t];
    if (t < 16) sb1[t] = b1[t];
    for (int e = t; e < 1024; e += 128) s2[e] = w2[e];
    if (t < 64) sb2[t] = b2[t];
    for (int e = t; e < 2048; e += 128) s3[e] = w3[e];
    if (t < 32) sb3[t] = b3[t];
    __syncthreads();
    int k = t & 15, lp = t >> 4;
    int p = blockIdx.x * 8 + lp, b = p >> 11;
    int j = g_idx[p*KNB + k];
    const float* xc = x + (size_t)p*3;
    const float* xn = x + (size_t)(b*NPT + j)*3;
    float in[6] = { xc[0], xc[1], xc[2], xn[0], xn[1], xn[2] };
    float h16[16];
    #pragma unroll
    for (int o4 = 0; o4 < 4; o4++) {
        float4 a = *(const float4*)(sb1 + o4*4);
        #pragma unroll
        for (int c = 0; c < 6; c++) {
            float4 w = *(const float4*)(s1 + c*16 + o4*4);
            float v = in[c];
            a.x += w.x*v; a.y += w.y*v; a.z += w.z*v; a.w += w.w*v;
        }
        h16[o4*4+0] = lrelu(a.x); h16[o4*4+1] = lrelu(a.y);
        h16[o4*4+2] = lrelu(a.z); h16[o4*4+3] = lrelu(a.w);
    }
    float h64[64];
    #pragma unroll
    for (int o4 = 0; o4 < 16; o4++) {
        float4 a = *(const float4*)(sb2 + o4*4);
        #pragma unroll
        for (int c = 0; c < 16; c++) {
            float4 w = *(const float4*)(s2 + c*64 + o4*4);
            float v = h16[c];
            a.x += w.x*v; a.y += w.y*v; a.z += w.z*v; a.w += w.w*v;
        }
        h64[o4*4+0] = lrelu(a.x); h64[o4*4+1] = lrelu(a.y);
        h64[o4*4+2] = lrelu(a.z); h64[o4*4+3] = lrelu(a.w);
    }
    float h32[32];
    #pragma unroll
    for (int o4 = 0; o4 < 8; o4++) {
        float4 a = *(const float4*)(sb3 + o4*4);
        #pragma unroll
        for (int c = 0; c < 64; c++) {
            float4 w = *(const float4*)(s3 + c*32 + o4*4);
            float v = h64[c];
            a.x += w.x*v; a.y += w.y*v; a.z += w.z*v; a.w += w.w*v;
        }
        h32[o4*4+0] = lrelu(a.x); h32[o4*4+1] = lrelu(a.y);
        h32[o4*4+2] = lrelu(a.z); h32[o4*4+3] = lrelu(a.w);
    }
    #pragma unroll
    for (int c = 0; c < 32; c++) {
        #pragma unroll
        for (int o = 8; o; o >>= 1) h32[c] += __shfl_xor_sync(0xffffffffu, h32[c], o);
    }
    if (k == 0) {
        float* outp = g_x2 + (size_t)p*32;
        #pragma unroll
        for (int c = 0; c < 32; c++) outp[c] = h32[c];
    }
}

// ======== factored layer-1 projections ========
template<int CIN, int COUT>
__global__ __launch_bounds__(256) void proj_kernel(
        const float* __restrict__ X, const float* __restrict__ W,
        const float* __restrict__ bias) {
    constexpr int OG = COUT/4;
    constexpr int R  = 256/OG;
    __shared__ float sin[R][CIN];
    int t = threadIdx.x, p0 = blockIdx.x * R;
    for (int e = t; e < R*CIN; e += 256) sin[e/CIN][e%CIN] = X[(size_t)p0*CIN + e];
    __syncthreads();
    int og = t % OG, r = t / OG;
    float4 aa = {0,0,0,0}, bb = {0,0,0,0};
    #pragma unroll 4
    for (int c = 0; c < CIN; c++) {
        float v = sin[r][c];
        float4 wa = *(const float4*)(W + (size_t)c*COUT + og*4);
        float4 wb = *(const float4*)(W + (size_t)(CIN+c)*COUT + og*4);
        aa.x += wa.x*v; aa.y += wa.y*v; aa.z += wa.z*v; aa.w += wa.w*v;
        bb.x += wb.x*v; bb.y += wb.y*v; bb.z += wb.z*v; bb.w += wb.w*v;
    }
    float4 b4 = *(const float4*)(bias + og*4);
    aa.x += b4.x; aa.y += b4.y; aa.z += b4.z; aa.w += b4.w;
    *(float4*)(g_A  + (size_t)(p0+r)*COUT + og*4) = aa;
    *(float4*)(g_Bf + (size_t)(p0+r)*COUT + og*4) = bb;
}

// ======== block 2 layer-2 via mma.sync, W double-buffered by cp.async ========
// floats: Hhi 0..4095 | Hlo 4096..8191 | Wbuf 8192..24575 (2 sets of Whi/Wlo 4096 each)
//         b2s 24576 | rowsrc 24704 ; stage reuses 0..16895
#define MLP2_SM (24832*4)
__global__ __launch_bounds__(512) void mlp2_mma(const float* __restrict__ b2) {
    extern __shared__ __align__(16) float sm[];
    float* Hhi = sm;
    float* b2s = sm + 24576;
    int*   rowsrc = (int*)(sm + 24704);
    int t = threadIdx.x, wid = t >> 5, lane = t & 31;
    int g = lane >> 2, tq = lane & 3;
    int rb = (wid & 3)*32, cb = (wid >> 2)*32;
    int p0 = blockIdx.x*8, b = p0 >> 11;
    uint32_t smb = smem_u32(sm);
    if (t < 128) {
        b2s[t] = b2[t];
        rowsrc[t] = b*NPT + g_idx[(p0 + (t>>4))*KNB + (t & 15)];
    }
    __syncthreads();

    auto prefetchW = [&](int ch, int bb) {
        uint32_t base = smb + (uint32_t)(8192 + bb*8192)*4u;
        for (int e = t; e < 2048; e += 512) {
            int arr = e >> 10, le = e & 1023, n = le >> 3, q = le & 7;
            const float* src = arr ? g_W2Tlo : g_W2Thi;
            uint32_t dst = base + (uint32_t)(arr*4096 + n*32 + 4*(q ^ (n & 7)))*4u;
            cpa16(dst, src + (size_t)n*256 + ch*32 + q*4);
        }
        CPA_COMMIT();
    };

    float c[2][4][4] = {};
    prefetchW(0, 0);
    #pragma unroll 1
    for (int ch = 0; ch < 8; ch++) {
        int cur = ch & 1;
        if (ch + 1 < 8) prefetchW(ch + 1, cur ^ 1);
        // H tile: gather + factored-add + lrelu + split (prev gemm done via loop-end sync)
        for (int e = t; e < 4096; e += 512) {
            int row = e >> 5, kq = e & 31, ci = ch*32 + kq;
            float v = lrelu(g_A[(size_t)(p0 + (row>>4))*256 + ci] + g_Bf[(size_t)rowsrc[row]*256 + ci]);
            float hi = tf32r(v);
            int si = swidx(row, kq);
            Hhi[si] = hi;
            Hhi[4096 + si] = tf32r(v - hi);
        }
        if (ch + 1 < 8) { CPA_WAIT1(); } else { CPA_WAIT0(); }
        __syncthreads();
        chunk_gemm(Hhi, sm + 8192 + cur*8192, c, rb, cb, g, tq);
        __syncthreads();
    }
    // epilogue: lrelu(+bias) -> stage -> sum 16 edges per point
    float* stage = sm;
    #pragma unroll
    for (int mt = 0; mt < 2; mt++) {
        int r0 = rb + mt*16 + g;
        #pragma unroll
        for (int nt = 0; nt < 4; nt++) {
            int cl = cb + nt*8 + 2*tq;
            float bb0 = b2s[cl], bb1 = b2s[cl + 1];
            stage[r0*132 + cl]     = lrelu(c[mt][nt][0] + bb0);
            stage[r0*132 + cl + 1] = lrelu(c[mt][nt][1] + bb1);
            stage[(r0+8)*132 + cl]     = lrelu(c[mt][nt][2] + bb0);
            stage[(r0+8)*132 + cl + 1] = lrelu(c[mt][nt][3] + bb1);
        }
    }
    __syncthreads();
    for (int o = t; o < 1024; o += 512) {
        int pl = o >> 7, cl = o & 127;
        const float* sp = stage + (pl*16)*132 + cl;
        float s = 0.f;
        #pragma unroll
        for (int kk = 0; kk < 16; kk++) s += sp[kk*132];
        g_x3[(size_t)(p0 + pl)*128 + cl] = s;
    }
}

// ======== block 3 (fully factored) ========
__global__ __launch_bounds__(128) void block3_kernel() {
    __shared__ int idxs[KNB];
    int p = blockIdx.x, t = threadIdx.x, b = p >> 11;
    if (t < KNB) idxs[t] = g_idx[p*KNB + t];
    __syncthreads();
    float a = g_A[(size_t)p*128 + t];
    float acc = 0.f;
    #pragma unroll
    for (int k = 0; k < KNB; k++)
        acc += lrelu(a + g_Bf[(size_t)(b*NPT + idxs[k])*128 + t]);
    g_x4[(size_t)p*128 + t] = acc;
}

// ======== max pool + head ========
__global__ __launch_bounds__(128) void maxpool_kernel() {
    int b = blockIdx.x, seg = blockIdx.y, t = threadIdx.x;
    const float* base = g_x4 + ((size_t)b*NPT + seg*128)*128 + t;
    float m = -FLT_MAX;
    #pragma unroll 8
    for (int r = 0; r < 128; r++) m = fmaxf(m, base[(size_t)r*128]);
    g_x5p[(b*16 + seg)*128 + t] = m;
}

__global__ __launch_bounds__(128) void final_kernel(
        const float* __restrict__ fc1w, const float* __restrict__ fc1b,
        const float* __restrict__ fc2w, const float* __restrict__ fc2b,
        const float* __restrict__ fc3w, const float* __restrict__ fc3b,
        float* __restrict__ out) {
    __shared__ float s5[128], s6[128], s7[128];
    int b = blockIdx.x, t = threadIdx.x;
    float m = -FLT_MAX;
    #pragma unroll
    for (int s = 0; s < 16; s++) m = fmaxf(m, g_x5p[(b*16+s)*128 + t]);
    s5[t] = m;
    __syncthreads();
    float a = fc1b[t];
    #pragma unroll 8
    for (int c = 0; c < 128; c++) a += fc1w[c*128+t]*s5[c];
    s6[t] = lrelu(a);
    __syncthreads();
    a = fc2b[t];
    #pragma unroll 8
    for (int c = 0; c < 128; c++) a += fc2w[c*128+t]*s6[c];
    s7[t] = lrelu(a);
    __syncthreads();
    float* ob = out + (size_t)b*6144;
    for (int o0 = 0; o0 < 6144; o0 += 512) {
        float acc[4];
        #pragma unroll
        for (int u = 0; u < 4; u++) acc[u] = fc3b[o0 + u*128 + t];
        #pragma unroll 4
        for (int c = 0; c < 128; c++) {
            float v = s7[c];
            const float* wr = fc3w + (size_t)c*6144 + o0 + t;
            #pragma unroll
            for (int u = 0; u < 4; u++) acc[u] += wr[u*128]*v;
        }
        #pragma unroll
        for (int u = 0; u < 4; u++) ob[o0 + u*128 + t] = acc[u];
    }
}

// ======== host ========
extern "C" void kernel_launch(void* const* d_in, const int* in_sizes, int n_in,
                              void* d_out, int out_size) {
    const float* x    = (const float*)d_in[0];
    const float* h1w1 = (const float*)d_in[1];
    const float* h1b1 = (const float*)d_in[2];
    const float* h1w2 = (const float*)d_in[3];
    const float* h1b2 = (const float*)d_in[4];
    const float* h1w3 = (const float*)d_in[5];
    const float* h1b3 = (const float*)d_in[6];
    const float* h2w1 = (const float*)d_in[7];
    const float* h2b1 = (const float*)d_in[8];
    const float* h2w2 = (const float*)d_in[9];
    const float* h2b2 = (const float*)d_in[10];
    const float* h3w1 = (const float*)d_in[11];
    const float* h3b1 = (const float*)d_in[12];
    const float* fc1w = (const float*)d_in[13];
    const float* fc1b = (const float*)d_in[14];
    const float* fc2w = (const float*)d_in[15];
    const float* fc2b = (const float*)d_in[16];
    const float* fc3w = (const float*)d_in[17];
    const float* fc3b = (const float*)d_in[18];
    float* out = (float*)d_out;

    cudaFuncSetAttribute(dist_mma<32>,  cudaFuncAttributeMaxDynamicSharedMemorySize, DIST_SM);
    cudaFuncSetAttribute(dist_mma<128>, cudaFuncAttributeMaxDynamicSharedMemorySize, DIST_SM);
    cudaFuncSetAttribute(mlp2_mma,      cudaFuncAttributeMaxDynamicSharedMemorySize, MLP2_SM);

    void* p2; cudaGetSymbolAddress(&p2, g_x2);
    void* p3; cudaGetSymbolAddress(&p3, g_x3);
    dim3 d3grid(32, 32, BATCH);
    dim3 trigrid(136, 1, BATCH);

    // stage 1 (C=3)
    sq_kernel<<<2048, 256>>>(x, 3);
    dist3_kernel<<<d3grid, 256>>>(x);
    topk_kernel<<<BN, 128>>>();
    mlp1_kernel<<<BN/8, 128>>>(x, h1w1, h1b1, h1w2, h1b2, h1w3, h1b3);

    // stage 2 (C=32)
    prep_kernel<32><<<BN/8, 256>>>((const float*)p2);
    dist_mma<32><<<trigrid, 512, DIST_SM>>>();
    topk_kernel<<<BN, 128>>>();
    proj_kernel<32, 256><<<BN/4, 256>>>((const float*)p2, h2w1, h2b1);
    prepw2_kernel<<<128, 256>>>(h2w2);
    mlp2_mma<<<BN/8, 512, MLP2_SM>>>(h2b2);

    // stage 3 (C=128)
    prep_kernel<128><<<BN/8, 256>>>((const float*)p3);
    dist_mma<128><<<trigrid, 512, DIST_SM>>>();
    topk_kernel<<<BN, 128>>>();
    proj_kernel<128, 128><<<BN/8, 256>>>((const float*)p3, h3w1, h3b1);
    block3_kernel<<<BN, 128>>>();

    // head
    maxpool_kernel<<<dim3(BATCH, 16), 128>>>();
    final_kernel<<<BATCH, 128>>>(fc1w, fc1b, fc2w, fc2b, fc3w, fc3b, out);
}

// round 9
// speedup vs baseline: 2.3317x; 1.0883x over previous
#include <cuda_runtime.h>
#include <float.h>
#include <stdint.h>

#define BATCH 8
#define NPT   2048
#define KNB   16
#define BN    (BATCH*NPT)

__device__ float g_D[(size_t)BATCH*NPT*NPT];
__device__ float g_sq[BN];
__device__ int   g_idx[BN*KNB];
__device__ float g_x2[BN*32];
__device__ float g_x3[BN*128];
__device__ float g_A [BN*256];
__device__ float g_Bf[BN*256];
__device__ float g_x4[BN*128];
__device__ float g_x5p[BATCH*16*128];
__device__ float g_x7[BATCH*128];
__device__ float g_Xhi[BN*128];
__device__ float g_Xlo[BN*128];
__device__ float g_W2Thi[128*256];   // [n][k], k contiguous
__device__ float g_W2Tlo[128*256];

__device__ __forceinline__ float lrelu(float v) { return v >= 0.f ? v : 0.01f*v; }
__device__ __forceinline__ float tf32r(float x) {
    uint32_t u; asm("cvt.rna.tf32.f32 %0, %1;" : "=r"(u) : "f"(x));
    return __uint_as_float(u);
}
__device__ __forceinline__ uint32_t smem_u32(const void* p) {
    uint32_t a;
    asm("{ .reg .u64 t; cvta.to.shared.u64 t, %1; cvt.u32.u64 %0, t; }" : "=r"(a) : "l"(p));
    return a;
}
__device__ __forceinline__ void cpa16(uint32_t saddr, const void* g) {
    asm volatile("cp.async.cg.shared.global [%0], [%1], 16;" :: "r"(saddr), "l"(g));
}
#define CPA_COMMIT() asm volatile("cp.async.commit_group;" ::: "memory")
#define CPA_WAIT0()  asm volatile("cp.async.wait_group 0;" ::: "memory")

__device__ __forceinline__ void mma8(float c[4], const uint32_t a[4], const uint32_t b[2]) {
    asm("mma.sync.aligned.m16n8k8.row.col.f32.tf32.tf32.f32 "
        "{%0,%1,%2,%3}, {%4,%5,%6,%7}, {%8,%9}, {%0,%1,%2,%3};"
        : "+f"(c[0]), "+f"(c[1]), "+f"(c[2]), "+f"(c[3])
        : "r"(a[0]), "r"(a[1]), "r"(a[2]), "r"(a[3]), "r"(b[0]), "r"(b[1]));
}

// XOR-swizzled index within a 128-row x 32-float K-major tile (conflict-free)
__device__ __forceinline__ int swidx(int row, int kq) {
    return row*32 + (kq ^ ((row & 7) << 2));
}

// warp GEMM over one K=32 chunk: 3-pass tf32 split, warp tile 32x32
// A: hi at +0, lo at +4096 ; B likewise
__device__ __forceinline__ void chunk_gemm(const float* __restrict__ A,
                                           const float* __restrict__ B,
                                           float (&c)[2][4][4],
                                           int rb, int cb, int g, int tq) {
    #pragma unroll
    for (int ks = 0; ks < 4; ks++) {
        int k0 = ks*8;
        uint32_t aH[2][4], aL[2][4], bH[4][2], bL[4][2];
        #pragma unroll
        for (int mt = 0; mt < 2; mt++) {
            int r0 = rb + mt*16 + g;
            int i00 = swidx(r0,   k0+tq), i01 = swidx(r0,   k0+tq+4);
            int i10 = swidx(r0+8, k0+tq), i11 = swidx(r0+8, k0+tq+4);
            aH[mt][0]=__float_as_uint(A[i00]); aH[mt][1]=__float_as_uint(A[i10]);
            aH[mt][2]=__float_as_uint(A[i01]); aH[mt][3]=__float_as_uint(A[i11]);
            aL[mt][0]=__float_as_uint(A[4096+i00]); aL[mt][1]=__float_as_uint(A[4096+i10]);
            aL[mt][2]=__float_as_uint(A[4096+i01]); aL[mt][3]=__float_as_uint(A[4096+i11]);
        }
        #pragma unroll
        for (int nt = 0; nt < 4; nt++) {
            int n0 = cb + nt*8 + g;
            int j0i = swidx(n0, k0+tq), j1i = swidx(n0, k0+tq+4);
            bH[nt][0]=__float_as_uint(B[j0i]); bH[nt][1]=__float_as_uint(B[j1i]);
            bL[nt][0]=__float_as_uint(B[4096+j0i]); bL[nt][1]=__float_as_uint(B[4096+j1i]);
        }
        #pragma unroll
        for (int mt = 0; mt < 2; mt++)
            #pragma unroll
            for (int nt = 0; nt < 4; nt++) {
                mma8(c[mt][nt], aH[mt], bH[nt]);
                mma8(c[mt][nt], aL[mt], bH[nt]);
                mma8(c[mt][nt], aH[mt], bL[nt]);
            }
    }
}

// ======== fused sq + tf32 split (warp per point) ========
template<int C>
__global__ void prep_kernel(const float* __restrict__ X) {
    int gw = (blockIdx.x*blockDim.x + threadIdx.x) >> 5, lane = threadIdx.x & 31;
    if (gw >= BN) return;
    const float* r = X + (size_t)gw*C;
    float acc = 0.f;
    #pragma unroll
    for (int c = lane; c < C; c += 32) {
        float v = r[c];
        acc += v*v;
        float hi = tf32r(v);
        g_Xhi[(size_t)gw*C + c] = hi;
        g_Xlo[(size_t)gw*C + c] = tf32r(v - hi);
    }
    #pragma unroll
    for (int o = 16; o; o >>= 1) acc += __shfl_xor_sync(0xffffffffu, acc, o);
    if (lane == 0) g_sq[gw] = acc;
}

__global__ __launch_bounds__(256) void prepw2_kernel(const float* __restrict__ W2) {
    int e = blockIdx.x*256 + threadIdx.x;   // 32768 = 256x128
    if (e >= 32768) return;
    int k = e >> 7, n = e & 127;
    float x = W2[e];
    float hi = tf32r(x);
    g_W2Thi[n*256 + k] = hi;
    g_W2Tlo[n*256 + k] = tf32r(x - hi);
}

// ======== dist C=3 (FFMA, norms inline) ========
__global__ __launch_bounds__(256) void dist3_kernel(const float* __restrict__ X) {
    __shared__ float As[3][65], Bs[3][65];
    int b = blockIdx.z, i0 = blockIdx.y*64, j0 = blockIdx.x*64;
    const float* Xb = X + (size_t)b*NPT*3;
    int t = threadIdx.x, tx = t & 15, ty = t >> 4;
    for (int e = t; e < 192; e += 256) {
        int r = e/3, c = e%3;
        As[c][r] = Xb[(size_t)(i0+r)*3 + c];
        Bs[c][r] = Xb[(size_t)(j0+r)*3 + c];
    }
    __syncthreads();
    float acc[4][4] = {};
    #pragma unroll
    for (int c = 0; c < 3; c++) {
        float av[4], bv[4];
        #pragma unroll
        for (int u = 0; u < 4; u++) { av[u] = As[c][ty*4+u]; bv[u] = Bs[c][tx*4+u]; }
        #pragma unroll
        for (int i = 0; i < 4; i++)
            #pragma unroll
            for (int j = 0; j < 4; j++) acc[i][j] += av[i]*bv[j];
    }
    float sj[4], si[4];
    #pragma unroll
    for (int u = 0; u < 4; u++) {
        int jr = tx*4 + u, ir = ty*4 + u;
        sj[u] = Bs[0][jr]*Bs[0][jr] + Bs[1][jr]*Bs[1][jr] + Bs[2][jr]*Bs[2][jr];
        si[u] = As[0][ir]*As[0][ir] + As[1][ir]*As[1][ir] + As[2][ir]*As[2][ir];
    }
    float* Db = g_D + (size_t)b*NPT*NPT;
    int j = j0 + tx*4;
    #pragma unroll
    for (int i = 0; i < 4; i++) {
        int ii = i0 + ty*4 + i;
        float4 o = { si[i]+sj[0]-2.f*acc[i][0], si[i]+sj[1]-2.f*acc[i][1],
                     si[i]+sj[2]-2.f*acc[i][2], si[i]+sj[3]-2.f*acc[i][3] };
        *(float4*)(Db + (size_t)ii*NPT + j) = o;
    }
}

// ======== dist via mma.sync, triangular grid, single-buffer, 3 CTA/SM ========
// floats: buf 16384 (AiH,AiL,BjH,BjL x4096) | stage reuses 0..16895 | sqi@16896 sqj@17024
#define DIST_SM (17152*4)
template<int C>
__global__ __launch_bounds__(512) void dist_mma() {
    extern __shared__ __align__(16) float sm[];
    float* sqi = sm + 16896; float* sqj = sm + 17024;
    int t = threadIdx.x, wid = t >> 5, lane = t & 31;
    int g = lane >> 2, tq = lane & 3;
    int rb = (wid & 3)*32, cb = (wid >> 2)*32;
    int b = blockIdx.z;
    int L = blockIdx.x, bi = 0;
    while (L >= 16 - bi) { L -= 16 - bi; bi++; }
    int bj = bi + L;
    int i0 = bi*128, j0 = bj*128;
    if (t < 128) { sqi[t] = g_sq[b*NPT + i0 + t]; sqj[t] = g_sq[b*NPT + j0 + t]; }
    const float* XiH = g_Xhi + (size_t)(b*NPT + i0)*C;
    const float* XiL = g_Xlo + (size_t)(b*NPT + i0)*C;
    const float* XjH = g_Xhi + (size_t)(b*NPT + j0)*C;
    const float* XjL = g_Xlo + (size_t)(b*NPT + j0)*C;
    uint32_t smb = smem_u32(sm);
    constexpr int NC = C/32;
    float c[2][4][4] = {};
    #pragma unroll 1
    for (int ch = 0; ch < NC; ch++) {
        __syncthreads();   // prev gemm reads done (also orders sq stores on first iter)
        for (int e = t; e < 4096; e += 512) {
            int arr = e >> 10, le = e & 1023, row = le >> 3, q = le & 7;
            const float* src = (arr == 0) ? XiH : (arr == 1) ? XiL : (arr == 2) ? XjH : XjL;
            uint32_t dst = smb + (uint32_t)(arr*4096 + row*32 + 4*(q ^ (row & 7)))*4u;
            cpa16(dst, src + (size_t)row*C + ch*32 + q*4);
        }
        CPA_COMMIT(); CPA_WAIT0();
        __syncthreads();
        chunk_gemm(sm, sm + 8192, c, rb, cb, g, tq);
    }
    __syncthreads();
    // stage (i-major), coalesced dump
    float* stage = sm;
    #pragma unroll
    for (int mt = 0; mt < 2; mt++) {
        int r0 = rb + mt*16 + g;
        float si0 = sqi[r0], si1 = sqi[r0 + 8];
        #pragma unroll
        for (int nt = 0; nt < 4; nt++) {
            int cl = cb + nt*8 + 2*tq;
            float sj0 = sqj[cl], sj1 = sqj[cl + 1];
            stage[r0*132 + cl]     = si0 + sj0 - 2.f*c[mt][nt][0];
            stage[r0*132 + cl + 1] = si0 + sj1 - 2.f*c[mt][nt][1];
            stage[(r0+8)*132 + cl]     = si1 + sj0 - 2.f*c[mt][nt][2];
            stage[(r0+8)*132 + cl + 1] = si1 + sj1 - 2.f*c[mt][nt][3];
        }
    }
    __syncthreads();
    float* Db = g_D + (size_t)b*NPT*NPT;
    for (int e = t; e < 4096; e += 512) {
        int r = e >> 5, q = e & 31;
        float4 v = *(const float4*)(stage + r*132 + q*4);
        *(float4*)(Db + (size_t)(i0 + r)*NPT + j0 + q*4) = v;
    }
    if (bi != bj) {
        __syncthreads();
        #pragma unroll
        for (int mt = 0; mt < 2; mt++) {
            int r0 = rb + mt*16 + g;
            float si0 = sqi[r0], si1 = sqi[r0 + 8];
            #pragma unroll
            for (int nt = 0; nt < 4; nt++) {
                int cl = cb + nt*8 + 2*tq;
                float sj0 = sqj[cl], sj1 = sqj[cl + 1];
                stage[cl*132 + r0]     = si0 + sj0 - 2.f*c[mt][nt][0];
                stage[(cl+1)*132 + r0] = si0 + sj1 - 2.f*c[mt][nt][1];
                stage[cl*132 + r0 + 8]     = si1 + sj0 - 2.f*c[mt][nt][2];
                stage[(cl+1)*132 + r0 + 8] = si1 + sj1 - 2.f*c[mt][nt][3];
            }
        }
        __syncthreads();
        for (int e = t; e < 4096; e += 512) {
            int r = e >> 5, q = e & 31;
            float4 v = *(const float4*)(stage + r*132 + q*4);
            *(float4*)(Db + (size_t)(j0 + r)*NPT + i0 + q*4) = v;
        }
    }
}

// ======== top-16 (256 threads) ========
#define PHYS(s) ((s) + ((s) >> 5))
__global__ __launch_bounds__(256) void topk_kernel() {
    __shared__ float sd[NPT + 64];
    __shared__ float rbest[8]; __shared__ int ribest[8];
    int row = blockIdx.x, t = threadIdx.x;
    const float* Dr = g_D + (size_t)row * NPT;
    for (int s = t; s < NPT; s += 256) sd[PHYS(s)] = Dr[s];
    __syncthreads();
    for (int it = 0; it < KNB; it++) {
        float best = FLT_MAX; int bi = NPT;
        for (int s = t; s < NPT; s += 256) {
            float v = sd[PHYS(s)];
            if (v < best) { best = v; bi = s; }
        }
        #pragma unroll
        for (int o = 16; o; o >>= 1) {
            float ov = __shfl_down_sync(0xffffffffu, best, o);
            int   oi = __shfl_down_sync(0xffffffffu, bi, o);
            if (ov < best || (ov == best && oi < bi)) { best = ov; bi = oi; }
        }
        if ((t & 31) == 0) { rbest[t>>5] = best; ribest[t>>5] = bi; }
        __syncthreads();
        if (t == 0) {
            #pragma unroll
            for (int w = 1; w < 8; w++)
                if (rbest[w] < best || (rbest[w] == best && ribest[w] < bi)) { best = rbest[w]; bi = ribest[w]; }
            g_idx[row*KNB + it] = bi;
            sd[PHYS(bi)] = FLT_MAX;
        }
        __syncthreads();
    }
}

// ======== block 1 edge MLP (chunked h64 -> ~80 regs) ========
__global__ __launch_bounds__(128) void mlp1_kernel(
        const float* __restrict__ x,
        const float* __restrict__ w1, const float* __restrict__ b1,
        const float* __restrict__ w2, const float* __restrict__ b2,
        const float* __restrict__ w3, const float* __restrict__ b3) {
    __shared__ float s1[96], sb1[16], s2[1024], sb2[64], s3[2048], sb3[32];
    int t = threadIdx.x;
    if (t < 96) s1[t] = w1[t];
    if (t < 16) sb1[t] = b1[t];
    for (int e = t; e < 1024; e += 128) s2[e] = w2[e];
    if (t < 64) sb2[t] = b2[t];
    for (int e = t; e < 2048; e += 128) s3[e] = w3[e];
    if (t < 32) sb3[t] = b3[t];
    __syncthreads();
    int k = t & 15, lp = t >> 4;
    int p = blockIdx.x * 8 + lp, b = p >> 11;
    int j = g_idx[p*KNB + k];
    const float* xc = x + (size_t)p*3;
    const float* xn = x + (size_t)(b*NPT + j)*3;
    float in[6] = { xc[0], xc[1], xc[2], xn[0], xn[1], xn[2] };
    float h16[16];
    #pragma unroll
    for (int o4 = 0; o4 < 4; o4++) {
        float4 a = *(const float4*)(sb1 + o4*4);
        #pragma unroll
        for (int c = 0; c < 6; c++) {
            float4 w = *(const float4*)(s1 + c*16 + o4*4);
            float v = in[c];
            a.x += w.x*v; a.y += w.y*v; a.z += w.z*v; a.w += w.w*v;
        }
        h16[o4*4+0] = lrelu(a.x); h16[o4*4+1] = lrelu(a.y);
        h16[o4*4+2] = lrelu(a.z); h16[o4*4+3] = lrelu(a.w);
    }
    float h32[32];
    #pragma unroll
    for (int o = 0; o < 32; o++) h32[o] = sb3[o];
    #pragma unroll
    for (int oc = 0; oc < 4; oc++) {
        float t16[16];
        #pragma unroll
        for (int o4 = 0; o4 < 4; o4++) {
            float4 a = *(const float4*)(sb2 + oc*16 + o4*4);
            #pragma unroll
            for (int c = 0; c < 16; c++) {
                float4 w = *(const float4*)(s2 + c*64 + oc*16 + o4*4);
                float v = h16[c];
                a.x += w.x*v; a.y += w.y*v; a.z += w.z*v; a.w += w.w*v;
            }
            t16[o4*4+0] = lrelu(a.x); t16[o4*4+1] = lrelu(a.y);
            t16[o4*4+2] = lrelu(a.z); t16[o4*4+3] = lrelu(a.w);
        }
        #pragma unroll
        for (int cc = 0; cc < 16; cc++) {
            float v = t16[cc];
            int c = oc*16 + cc;
            #pragma unroll
            for (int o4 = 0; o4 < 8; o4++) {
                float4 w = *(const float4*)(s3 + c*32 + o4*4);
                h32[o4*4+0] += w.x*v; h32[o4*4+1] += w.y*v;
                h32[o4*4+2] += w.z*v; h32[o4*4+3] += w.w*v;
            }
        }
    }
    // lrelu then sum over k within 16-lane groups
    #pragma unroll
    for (int c = 0; c < 32; c++) {
        float v = lrelu(h32[c]);
        #pragma unroll
        for (int o = 8; o; o >>= 1) v += __shfl_xor_sync(0xffffffffu, v, o);
        h32[c] = v;
    }
    if (k == 0) {
        float* outp = g_x2 + (size_t)p*32;
        #pragma unroll
        for (int c = 0; c < 32; c++) outp[c] = h32[c];
    }
}

// ======== factored layer-1 projections ========
template<int CIN, int COUT>
__global__ __launch_bounds__(256) void proj_kernel(
        const float* __restrict__ X, const float* __restrict__ W,
        const float* __restrict__ bias) {
    constexpr int OG = COUT/4;
    constexpr int R  = 256/OG;
    __shared__ float sin[R][CIN];
    int t = threadIdx.x, p0 = blockIdx.x * R;
    for (int e = t; e < R*CIN; e += 256) sin[e/CIN][e%CIN] = X[(size_t)p0*CIN + e];
    __syncthreads();
    int og = t % OG, r = t / OG;
    float4 aa = {0,0,0,0}, bb = {0,0,0,0};
    #pragma unroll 4
    for (int c = 0; c < CIN; c++) {
        float v = sin[r][c];
        float4 wa = *(const float4*)(W + (size_t)c*COUT + og*4);
        float4 wb = *(const float4*)(W + (size_t)(CIN+c)*COUT + og*4);
        aa.x += wa.x*v; aa.y += wa.y*v; aa.z += wa.z*v; aa.w += wa.w*v;
        bb.x += wb.x*v; bb.y += wb.y*v; bb.z += wb.z*v; bb.w += wb.w*v;
    }
    float4 b4 = *(const float4*)(bias + og*4);
    aa.x += b4.x; aa.y += b4.y; aa.z += b4.z; aa.w += b4.w;
    *(float4*)(g_A  + (size_t)(p0+r)*COUT + og*4) = aa;
    *(float4*)(g_Bf + (size_t)(p0+r)*COUT + og*4) = bb;
}

// ======== block 2 layer-2 via mma.sync, single-buffer, 3 CTA/SM ========
// floats: H 0..8191 (hi,lo) | W 8192..16383 (hi,lo) | stage reuse 0..16895 | b2s@16896 rowsrc@17024
#define MLP2_SM (17152*4)
__global__ __launch_bounds__(512) void mlp2_mma(const float* __restrict__ b2) {
    extern __shared__ __align__(16) float sm[];
    float* Hhi = sm;
    float* b2s = sm + 16896;
    int*   rowsrc = (int*)(sm + 17024);
    int t = threadIdx.x, wid = t >> 5, lane = t & 31;
    int g = lane >> 2, tq = lane & 3;
    int rb = (wid & 3)*32, cb = (wid >> 2)*32;
    int p0 = blockIdx.x*8, b = p0 >> 11;
    uint32_t smb = smem_u32(sm);
    if (t < 128) {
        b2s[t] = b2[t];
        rowsrc[t] = b*NPT + g_idx[(p0 + (t>>4))*KNB + (t & 15)];
    }
    __syncthreads();
    float c[2][4][4] = {};
    #pragma unroll 1
    for (int ch = 0; ch < 8; ch++) {
        // W tile via cp.async
        for (int e = t; e < 2048; e += 512) {
            int arr = e >> 10, le = e & 1023, n = le >> 3, q = le & 7;
            const float* src = arr ? g_W2Tlo : g_W2Thi;
            uint32_t dst = smb + (uint32_t)(8192 + arr*4096 + n*32 + 4*(q ^ (n & 7)))*4u;
            cpa16(dst, src + (size_t)n*256 + ch*32 + q*4);
        }
        CPA_COMMIT();
        // H tile: gather + factored-add + lrelu + split
        for (int e = t; e < 4096; e += 512) {
            int row = e >> 5, kq = e & 31, ci = ch*32 + kq;
            float v = lrelu(g_A[(size_t)(p0 + (row>>4))*256 + ci] + g_Bf[(size_t)rowsrc[row]*256 + ci]);
            float hi = tf32r(v);
            int si = swidx(row, kq);
            Hhi[si] = hi;
            Hhi[4096 + si] = tf32r(v - hi);
        }
        CPA_WAIT0();
        __syncthreads();
        chunk_gemm(Hhi, sm + 8192, c, rb, cb, g, tq);
        __syncthreads();   // gemm reads done before next fill
    }
    // epilogue: lrelu(+bias) -> stage -> sum 16 edges per point
    float* stage = sm;
    #pragma unroll
    for (int mt = 0; mt < 2; mt++) {
        int r0 = rb + mt*16 + g;
        #pragma unroll
        for (int nt = 0; nt < 4; nt++) {
            int cl = cb + nt*8 + 2*tq;
            float bb0 = b2s[cl], bb1 = b2s[cl + 1];
            stage[r0*132 + cl]     = lrelu(c[mt][nt][0] + bb0);
            stage[r0*132 + cl + 1] = lrelu(c[mt][nt][1] + bb1);
            stage[(r0+8)*132 + cl]     = lrelu(c[mt][nt][2] + bb0);
            stage[(r0+8)*132 + cl + 1] = lrelu(c[mt][nt][3] + bb1);
        }
    }
    __syncthreads();
    for (int o = t; o < 1024; o += 512) {
        int pl = o >> 7, cl = o & 127;
        const float* sp = stage + (pl*16)*132 + cl;
        float s = 0.f;
        #pragma unroll
        for (int kk = 0; kk < 16; kk++) s += sp[kk*132];
        g_x3[(size_t)(p0 + pl)*128 + cl] = s;
    }
}

// ======== block 3 (fully factored) ========
__global__ __launch_bounds__(128) void block3_kernel() {
    __shared__ int idxs[KNB];
    int p = blockIdx.x, t = threadIdx.x, b = p >> 11;
    if (t < KNB) idxs[t] = g_idx[p*KNB + t];
    __syncthreads();
    float a = g_A[(size_t)p*128 + t];
    float acc = 0.f;
    #pragma unroll
    for (int k = 0; k < KNB; k++)
        acc += lrelu(a + g_Bf[(size_t)(b*NPT + idxs[k])*128 + t]);
    g_x4[(size_t)p*128 + t] = acc;
}

// ======== max pool + head ========
__global__ __launch_bounds__(128) void maxpool_kernel() {
    int b = blockIdx.x, seg = blockIdx.y, t = threadIdx.x;
    const float* base = g_x4 + ((size_t)b*NPT + seg*128)*128 + t;
    float m = -FLT_MAX;
    #pragma unroll 8
    for (int r = 0; r < 128; r++) m = fmaxf(m, base[(size_t)r*128]);
    g_x5p[(b*16 + seg)*128 + t] = m;
}

__global__ __launch_bounds__(128) void final12_kernel(
        const float* __restrict__ fc1w, const float* __restrict__ fc1b,
        const float* __restrict__ fc2w, const float* __restrict__ fc2b) {
    __shared__ float s5[128], s6[128];
    int b = blockIdx.x, t = threadIdx.x;
    float m = -FLT_MAX;
    #pragma unroll
    for (int s = 0; s < 16; s++) m = fmaxf(m, g_x5p[(b*16+s)*128 + t]);
    s5[t] = m;
    __syncthreads();
    float a = fc1b[t];
    #pragma unroll 8
    for (int c = 0; c < 128; c++) a += fc1w[c*128+t]*s5[c];
    s6[t] = lrelu(a);
    __syncthreads();
    a = fc2b[t];
    #pragma unroll 8
    for (int c = 0; c < 128; c++) a += fc2w[c*128+t]*s6[c];
    g_x7[b*128 + t] = lrelu(a);
}

__global__ __launch_bounds__(128) void fc3_kernel(
        const float* __restrict__ fc3w, const float* __restrict__ fc3b,
        float* __restrict__ out) {
    __shared__ float s7[128];
    int b = blockIdx.x, seg = blockIdx.y, t = threadIdx.x;
    s7[t] = g_x7[b*128 + t];
    __syncthreads();
    int o0 = seg*512;
    float acc[4];
    #pragma unroll
    for (int u = 0; u < 4; u++) acc[u] = fc3b[o0 + u*128 + t];
    #pragma unroll 4
    for (int c = 0; c < 128; c++) {
        float v = s7[c];
        const float* wr = fc3w + (size_t)c*6144 + o0 + t;
        #pragma unroll
        for (int u = 0; u < 4; u++) acc[u] += wr[u*128]*v;
    }
    float* ob = out + (size_t)b*6144 + o0;
    #pragma unroll
    for (int u = 0; u < 4; u++) ob[u*128 + t] = acc[u];
}

// ======== host ========
extern "C" void kernel_launch(void* const* d_in, const int* in_sizes, int n_in,
                              void* d_out, int out_size) {
    const float* x    = (const float*)d_in[0];
    const float* h1w1 = (const float*)d_in[1];
    const float* h1b1 = (const float*)d_in[2];
    const float* h1w2 = (const float*)d_in[3];
    const float* h1b2 = (const float*)d_in[4];
    const float* h1w3 = (const float*)d_in[5];
    const float* h1b3 = (const float*)d_in[6];
    const float* h2w1 = (const float*)d_in[7];
    const float* h2b1 = (const float*)d_in[8];
    const float* h2w2 = (const float*)d_in[9];
    const float* h2b2 = (const float*)d_in[10];
    const float* h3w1 = (const float*)d_in[11];
    const float* h3b1 = (const float*)d_in[12];
    const float* fc1w = (const float*)d_in[13];
    const float* fc1b = (const float*)d_in[14];
    const float* fc2w = (const float*)d_in[15];
    const float* fc2b = (const float*)d_in[16];
    const float* fc3w = (const float*)d_in[17];
    const float* fc3b = (const float*)d_in[18];
    float* out = (float*)d_out;

    cudaFuncSetAttribute(dist_mma<32>,  cudaFuncAttributeMaxDynamicSharedMemorySize, DIST_SM);
    cudaFuncSetAttribute(dist_mma<128>, cudaFuncAttributeMaxDynamicSharedMemorySize, DIST_SM);
    cudaFuncSetAttribute(mlp2_mma,      cudaFuncAttributeMaxDynamicSharedMemorySize, MLP2_SM);

    void* p2; cudaGetSymbolAddress(&p2, g_x2);
    void* p3; cudaGetSymbolAddress(&p3, g_x3);
    dim3 d3grid(32, 32, BATCH);
    dim3 trigrid(136, 1, BATCH);

    // stage 1 (C=3)
    dist3_kernel<<<d3grid, 256>>>(x);
    topk_kernel<<<BN, 256>>>();
    mlp1_kernel<<<BN/8, 128>>>(x, h1w1, h1b1, h1w2, h1b2, h1w3, h1b3);

    // stage 2 (C=32)
    prep_kernel<32><<<BN/8, 256>>>((const float*)p2);
    dist_mma<32><<<trigrid, 512, DIST_SM>>>();
    topk_kernel<<<BN, 256>>>();
    proj_kernel<32, 256><<<BN/4, 256>>>((const float*)p2, h2w1, h2b1);
    prepw2_kernel<<<128, 256>>>(h2w2);
    mlp2_mma<<<BN/8, 512, MLP2_SM>>>(h2b2);

    // stage 3 (C=128)
    prep_kernel<128><<<BN/8, 256>>>((const float*)p3);
    dist_mma<128><<<trigrid, 512, DIST_SM>>>();
    topk_kernel<<<BN, 256>>>();
    proj_kernel<128, 128><<<BN/8, 256>>>((const float*)p3, h3w1, h3b1);
    block3_kernel<<<BN, 128>>>();

    // head
    maxpool_kernel<<<dim3(BATCH, 16), 128>>>();
    final12_kernel<<<BATCH, 128>>>(fc1w, fc1b, fc2w, fc2b);
    fc3_kernel<<<dim3(BATCH, 12), 128>>>(fc3w, fc3b, out);
}